// round 3
// baseline (speedup 1.0000x reference)
#include <cuda_runtime.h>
#include <cuda_bf16.h>
#include <cstdint>

#define BB 2
#define HH 8
#define DH 64
#define DM 512
#define NQ 4096
#define NK 4096

// -------- scratch (no allocations allowed) --------
__device__ float g_qh[BB*HH*NQ*DH];
__device__ float g_kh[BB*HH*NK*DH];
__device__ float g_vh[BB*HH*NK*DH];
__device__ float g_o [BB*HH*NQ*DH];   // UNNORMALIZED O (E @ V)
__device__ float g_zi[BB*HH*NQ];      // 1 / rowsum(exp(S))

__device__ __forceinline__ float to_tf32(float x) {
    float r;
    asm("cvt.rna.tf32.f32 %0, %1;" : "=f"(r) : "f"(x));
    return r;
}

// D += A(16x8) * B(8x8), tf32 inputs, fp32 accum
__device__ __forceinline__ void mma8(float* d, const float* a, const float* b) {
    asm("mma.sync.aligned.m16n8k8.row.col.f32.tf32.tf32.f32 "
        "{%0,%1,%2,%3}, {%4,%5,%6,%7}, {%8,%9}, {%0,%1,%2,%3};"
        : "+f"(d[0]), "+f"(d[1]), "+f"(d[2]), "+f"(d[3])
        : "r"(__float_as_uint(a[0])), "r"(__float_as_uint(a[1])),
          "r"(__float_as_uint(a[2])), "r"(__float_as_uint(a[3])),
          "r"(__float_as_uint(b[0])), "r"(__float_as_uint(b[1])));
}

// ============================================================
// QKV projection: Y[b,h,n,d] = X[row] @ W^T + bias, scattered head-major.
// ============================================================
__global__ __launch_bounds__(256) void proj_head_kernel(
    const float* __restrict__ X, const float* __restrict__ W,
    const float* __restrict__ bias, int sel)
{
    float* dst = sel == 0 ? g_qh : (sel == 1 ? g_kh : g_vh);
    __shared__ float As[128][36];
    __shared__ float Ws[64][36];
    int tid = threadIdx.x;
    int lane = tid & 31, warp = tid >> 5;
    int g = lane >> 2, t = lane & 3;
    int wm = warp >> 1, wn = warp & 1;
    int m0 = blockIdx.x * 128;
    int h  = blockIdx.y;

    float acc[2][4][4];
#pragma unroll
    for (int i = 0; i < 2; i++)
#pragma unroll
        for (int j = 0; j < 4; j++)
#pragma unroll
            for (int c = 0; c < 4; c++) acc[i][j][c] = 0.f;

    int rl = tid >> 3, cl = (tid & 7) * 4;
    for (int k0 = 0; k0 < DM; k0 += 32) {
#pragma unroll
        for (int i = 0; i < 4; i++) {
            int r = rl + i * 32;
            float4 v = *(const float4*)(X + (size_t)(m0 + r) * DM + k0 + cl);
            As[r][cl]   = to_tf32(v.x);
            As[r][cl+1] = to_tf32(v.y);
            As[r][cl+2] = to_tf32(v.z);
            As[r][cl+3] = to_tf32(v.w);
        }
#pragma unroll
        for (int i = 0; i < 2; i++) {
            int r = rl + i * 32;
            float4 v = *(const float4*)(W + (size_t)(h * 64 + r) * DM + k0 + cl);
            Ws[r][cl]   = to_tf32(v.x);
            Ws[r][cl+1] = to_tf32(v.y);
            Ws[r][cl+2] = to_tf32(v.z);
            Ws[r][cl+3] = to_tf32(v.w);
        }
        __syncthreads();
#pragma unroll
        for (int kk = 0; kk < 4; kk++) {
            float a[2][4];
#pragma unroll
            for (int mt = 0; mt < 2; mt++) {
                int rb = wm * 32 + mt * 16;
                a[mt][0] = As[rb + g][kk*8 + t];
                a[mt][1] = As[rb + 8 + g][kk*8 + t];
                a[mt][2] = As[rb + g][kk*8 + t + 4];
                a[mt][3] = As[rb + 8 + g][kk*8 + t + 4];
            }
            float bf[4][2];
#pragma unroll
            for (int nt = 0; nt < 4; nt++) {
                int nl = wn * 32 + nt * 8 + g;
                bf[nt][0] = Ws[nl][kk*8 + t];
                bf[nt][1] = Ws[nl][kk*8 + t + 4];
            }
#pragma unroll
            for (int mt = 0; mt < 2; mt++)
#pragma unroll
                for (int nt = 0; nt < 4; nt++)
                    mma8(acc[mt][nt], a[mt], bf[nt]);
        }
        __syncthreads();
    }
#pragma unroll
    for (int mt = 0; mt < 2; mt++) {
        int r0 = m0 + wm * 32 + mt * 16 + g;
        int r1 = r0 + 8;
#pragma unroll
        for (int nt = 0; nt < 4; nt++) {
            int col = wn * 32 + nt * 8 + 2 * t;
            float b0v = bias[h * 64 + col], b1v = bias[h * 64 + col + 1];
            int b_ = r0 >> 12, q_ = r0 & 4095;
            float* p = dst + (size_t)((b_ * HH + h) * NQ + q_) * DH + col;
            p[0] = acc[mt][nt][0] + b0v;
            p[1] = acc[mt][nt][1] + b1v;
            b_ = r1 >> 12; q_ = r1 & 4095;
            p = dst + (size_t)((b_ * HH + h) * NQ + q_) * DH + col;
            p[0] = acc[mt][nt][2] + b0v;
            p[1] = acc[mt][nt][3] + b1v;
        }
    }
}

// ============================================================
// Output projection: output = (concat_heads(g_o) * invZ) @ Wo^T + bo
// ============================================================
__global__ __launch_bounds__(256) void proj_out_kernel(
    const float* __restrict__ W, const float* __restrict__ bias,
    float* __restrict__ Y)
{
    __shared__ float As[128][36];
    __shared__ float Ws[64][36];
    int tid = threadIdx.x;
    int lane = tid & 31, warp = tid >> 5;
    int g = lane >> 2, t = lane & 3;
    int wm = warp >> 1, wn = warp & 1;
    int m0 = blockIdx.x * 128;
    int n0 = blockIdx.y * 64;

    float acc[2][4][4];
#pragma unroll
    for (int i = 0; i < 2; i++)
#pragma unroll
        for (int j = 0; j < 4; j++)
#pragma unroll
            for (int c = 0; c < 4; c++) acc[i][j][c] = 0.f;

    int rl = tid >> 3, cl = (tid & 7) * 4;
    for (int k0 = 0; k0 < DM; k0 += 32) {
        int head = k0 >> 6;
        int dd = (k0 & 63) + cl;
#pragma unroll
        for (int i = 0; i < 4; i++) {
            int r = rl + i * 32;
            int row = m0 + r;
            int b_ = row >> 12, q_ = row & 4095;
            size_t hb = (size_t)(b_ * HH + head) * NQ + q_;
            float zi = g_zi[hb];
            float4 v = *(const float4*)(g_o + hb * DH + dd);
            As[r][cl]   = to_tf32(v.x * zi);
            As[r][cl+1] = to_tf32(v.y * zi);
            As[r][cl+2] = to_tf32(v.z * zi);
            As[r][cl+3] = to_tf32(v.w * zi);
        }
#pragma unroll
        for (int i = 0; i < 2; i++) {
            int r = rl + i * 32;
            float4 v = *(const float4*)(W + (size_t)(n0 + r) * DM + k0 + cl);
            Ws[r][cl]   = to_tf32(v.x);
            Ws[r][cl+1] = to_tf32(v.y);
            Ws[r][cl+2] = to_tf32(v.z);
            Ws[r][cl+3] = to_tf32(v.w);
        }
        __syncthreads();
#pragma unroll
        for (int kk = 0; kk < 4; kk++) {
            float a[2][4];
#pragma unroll
            for (int mt = 0; mt < 2; mt++) {
                int rb = wm * 32 + mt * 16;
                a[mt][0] = As[rb + g][kk*8 + t];
                a[mt][1] = As[rb + 8 + g][kk*8 + t];
                a[mt][2] = As[rb + g][kk*8 + t + 4];
                a[mt][3] = As[rb + 8 + g][kk*8 + t + 4];
            }
            float bf[4][2];
#pragma unroll
            for (int nt = 0; nt < 4; nt++) {
                int nl = wn * 32 + nt * 8 + g;
                bf[nt][0] = Ws[nl][kk*8 + t];
                bf[nt][1] = Ws[nl][kk*8 + t + 4];
            }
#pragma unroll
            for (int mt = 0; mt < 2; mt++)
#pragma unroll
                for (int nt = 0; nt < 4; nt++)
                    mma8(acc[mt][nt], a[mt], bf[nt]);
        }
        __syncthreads();
    }
#pragma unroll
    for (int mt = 0; mt < 2; mt++) {
        int r0 = m0 + wm * 32 + mt * 16 + g;
        int r1 = r0 + 8;
#pragma unroll
        for (int nt = 0; nt < 4; nt++) {
            int col = wn * 32 + nt * 8 + 2 * t;
            float b0v = bias[n0 + col], b1v = bias[n0 + col + 1];
            float* p = Y + (size_t)r0 * DM + n0 + col;
            p[0] = acc[mt][nt][0] + b0v;
            p[1] = acc[mt][nt][1] + b1v;
            p = Y + (size_t)r1 * DM + n0 + col;
            p[0] = acc[mt][nt][2] + b0v;
            p[1] = acc[mt][nt][3] + b1v;
        }
    }
}

// ============================================================
// Attention (single pass, 512 threads, 128-row Q tile):
//  S phase: 16 warps = 4(wm) x 4(wn), each 32x32 of the 128x128 S tile.
//  AV phase: warp (wm,wn) owns O rows wm*32..+32, cols wn*16..+16,
//            iterates full k=0..127 (no cross-warp reduction).
// Writes UNNORMALIZED E to attn, 1/Z to g_zi, unnormalized O to g_o.
// ============================================================
// smem float offsets
#define SM_Q 0            // [128][68] = 8704
#define SM_K 8704         // [128][68] = 8704
#define SM_V 17408        // [128][68] = 8704
#define SM_P 26112        // [128][132] = 16896
#define SM_Z 43008        // [128]
#define SM_M 43136        // [128][32] u32 = 4096
#define SMEM_FLOATS 47232
#define SMEM_BYTES (SMEM_FLOATS*4)   // 188928

__global__ __launch_bounds__(512, 1) void attn_kernel(
    const unsigned char* __restrict__ mask, float* __restrict__ attn)
{
    extern __shared__ float sm[];
    float* Qs = sm + SM_Q;
    float* Ks = sm + SM_K;
    float* Vs = sm + SM_V;
    float* Ps = sm + SM_P;
    float* Zs = sm + SM_Z;
    unsigned int* Ms = (unsigned int*)(sm + SM_M);

    int tid = threadIdx.x;
    int lane = tid & 31, warp = tid >> 5;
    int g = lane >> 2, t = lane & 3;
    int wm = warp >> 2;   // 0..3 : 32-row strip
    int wn = warp & 3;    // 0..3 : S 32-col chunk / O 16-col slice
    int q0 = blockIdx.x * 128;
    int bh = blockIdx.y;
    int b = bh >> 3, h = bh & 7;
    size_t headbase = (size_t)(b * HH + h) * NQ * DH;
    const unsigned char* mbase = mask + (size_t)(b * NQ + q0) * NK;

    // load Q tile (pre-scaled by 1/8), resident for whole kernel
#pragma unroll
    for (int j = 0; j < 4; j++) {
        int idx = tid + j * 512;
        int r = idx >> 4, c = (idx & 15) * 4;
        float4 v = *(const float4*)(g_qh + headbase + (size_t)(q0 + r) * DH + c);
        Qs[r*68 + c]   = to_tf32(v.x * 0.125f);
        Qs[r*68 + c+1] = to_tf32(v.y * 0.125f);
        Qs[r*68 + c+2] = to_tf32(v.z * 0.125f);
        Qs[r*68 + c+3] = to_tf32(v.w * 0.125f);
    }
    if (tid < 128) Zs[tid] = 0.f;

    float oacc[2][2][4];
#pragma unroll
    for (int i = 0; i < 2; i++)
#pragma unroll
        for (int j = 0; j < 2; j++)
#pragma unroll
            for (int c = 0; c < 4; c++) oacc[i][j][c] = 0.f;

    int rbase = wm * 32;

    for (int kt = 0; kt < NK / 128; kt++) {
        int k0 = kt * 128;
        __syncthreads();
        // load K,V tiles
#pragma unroll
        for (int j = 0; j < 4; j++) {
            int idx = tid + j * 512;
            int r = idx >> 4, c = (idx & 15) * 4;
            float4 v = *(const float4*)(g_kh + headbase + (size_t)(k0 + r) * DH + c);
            Ks[r*68 + c]   = to_tf32(v.x);
            Ks[r*68 + c+1] = to_tf32(v.y);
            Ks[r*68 + c+2] = to_tf32(v.z);
            Ks[r*68 + c+3] = to_tf32(v.w);
            float4 w = *(const float4*)(g_vh + headbase + (size_t)(k0 + r) * DH + c);
            Vs[r*68 + c]   = to_tf32(w.x);
            Vs[r*68 + c+1] = to_tf32(w.y);
            Vs[r*68 + c+2] = to_tf32(w.z);
            Vs[r*68 + c+3] = to_tf32(w.w);
        }
        // load mask tile
#pragma unroll
        for (int j = 0; j < 8; j++) {
            int idx = tid + j * 512;
            int r = idx >> 5, c = idx & 31;
            Ms[r * 32 + c] = *(const unsigned int*)(mbase + (size_t)r * NK + k0 + c * 4);
        }
        __syncthreads();

        // ---- S = Q K^T ----
        float sacc[2][4][4];
#pragma unroll
        for (int i = 0; i < 2; i++)
#pragma unroll
            for (int j = 0; j < 4; j++)
#pragma unroll
                for (int c = 0; c < 4; c++) sacc[i][j][c] = 0.f;
#pragma unroll
        for (int kk = 0; kk < 8; kk++) {
            float a[2][4];
#pragma unroll
            for (int mt = 0; mt < 2; mt++) {
                int rb = rbase + mt * 16;
                a[mt][0] = Qs[(rb + g) * 68 + kk*8 + t];
                a[mt][1] = Qs[(rb + 8 + g) * 68 + kk*8 + t];
                a[mt][2] = Qs[(rb + g) * 68 + kk*8 + t + 4];
                a[mt][3] = Qs[(rb + 8 + g) * 68 + kk*8 + t + 4];
            }
            float bf[4][2];
#pragma unroll
            for (int nt = 0; nt < 4; nt++) {
                int nl = wn * 32 + nt * 8 + g;
                bf[nt][0] = Ks[nl * 68 + kk*8 + t];
                bf[nt][1] = Ks[nl * 68 + kk*8 + t + 4];
            }
#pragma unroll
            for (int mt = 0; mt < 2; mt++)
#pragma unroll
                for (int nt = 0; nt < 4; nt++)
                    mma8(sacc[mt][nt], a[mt], bf[nt]);
        }

        // ---- E = exp(S) (masked), Z accumulate, stage to Ps ----
        const unsigned char* Mb = (const unsigned char*)Ms;
        float rsum[4] = {0.f, 0.f, 0.f, 0.f};
#pragma unroll
        for (int mt = 0; mt < 2; mt++) {
            int r0 = rbase + mt * 16 + g, r1 = r0 + 8;
#pragma unroll
            for (int nt = 0; nt < 4; nt++) {
                int c0 = wn * 32 + nt * 8 + 2 * t;
                float p00 = Mb[r0*128 + c0]     ? 0.f : __expf(sacc[mt][nt][0]);
                float p01 = Mb[r0*128 + c0 + 1] ? 0.f : __expf(sacc[mt][nt][1]);
                float p10 = Mb[r1*128 + c0]     ? 0.f : __expf(sacc[mt][nt][2]);
                float p11 = Mb[r1*128 + c0 + 1] ? 0.f : __expf(sacc[mt][nt][3]);
                rsum[mt*2]     += p00 + p01;
                rsum[mt*2 + 1] += p10 + p11;
                Ps[r0*132 + c0]     = p00;
                Ps[r0*132 + c0 + 1] = p01;
                Ps[r1*132 + c0]     = p10;
                Ps[r1*132 + c0 + 1] = p11;
            }
        }
#pragma unroll
        for (int i = 0; i < 4; i++) {
            rsum[i] += __shfl_xor_sync(0xffffffffu, rsum[i], 1);
            rsum[i] += __shfl_xor_sync(0xffffffffu, rsum[i], 2);
        }
        if (t == 0) {
            atomicAdd(&Zs[rbase + g],      rsum[0]);
            atomicAdd(&Zs[rbase + 8 + g],  rsum[1]);
            atomicAdd(&Zs[rbase + 16 + g], rsum[2]);
            atomicAdd(&Zs[rbase + 24 + g], rsum[3]);
        }
        __syncthreads();

        // ---- write UNNORMALIZED E tile (attn layout [h*BB+b, q, k]) ----
        size_t abase = ((size_t)(h * BB + b) * NQ + q0) * NK + k0;
#pragma unroll
        for (int j = 0; j < 8; j++) {
            int idx = tid + j * 512;
            int r = idx >> 5, c = (idx & 31) * 4;
            float4 v = *(const float4*)(Ps + r * 132 + c);
            *(float4*)(attn + abase + (size_t)r * NK + c) = v;
        }

        // ---- O += E @ V : warp owns rows wm*32..+32, cols wn*16..+16 ----
#pragma unroll
        for (int kk = 0; kk < 16; kk++) {
            int kb = kk * 8;
            float a[2][4];
#pragma unroll
            for (int mt = 0; mt < 2; mt++) {
                int rb = rbase + mt * 16;
                a[mt][0] = to_tf32(Ps[(rb + g) * 132 + kb + t]);
                a[mt][1] = to_tf32(Ps[(rb + 8 + g) * 132 + kb + t]);
                a[mt][2] = to_tf32(Ps[(rb + g) * 132 + kb + t + 4]);
                a[mt][3] = to_tf32(Ps[(rb + 8 + g) * 132 + kb + t + 4]);
            }
            float bf[2][2];
#pragma unroll
            for (int nt = 0; nt < 2; nt++) {
                int nc = wn * 16 + nt * 8 + g;
                bf[nt][0] = Vs[(kb + t) * 68 + nc];
                bf[nt][1] = Vs[(kb + t + 4) * 68 + nc];
            }
#pragma unroll
            for (int mt = 0; mt < 2; mt++)
#pragma unroll
                for (int nt = 0; nt < 2; nt++)
                    mma8(oacc[mt][nt], a[mt], bf[nt]);
        }
    }

    // ---- write 1/Z ----
    __syncthreads();
    if (tid < 128) {
        g_zi[(size_t)(b * HH + h) * NQ + q0 + tid] = 1.0f / Zs[tid];
    }

    // ---- stage O to smem (disjoint ownership, no atomics), then coalesced write
    float* Os = Ps;   // reuse [128][68]
#pragma unroll
    for (int mt = 0; mt < 2; mt++) {
        int r0 = rbase + mt * 16 + g, r1 = r0 + 8;
#pragma unroll
        for (int nt = 0; nt < 2; nt++) {
            int c0 = wn * 16 + nt * 8 + 2 * t;
            Os[r0 * 68 + c0]     = oacc[mt][nt][0];
            Os[r0 * 68 + c0 + 1] = oacc[mt][nt][1];
            Os[r1 * 68 + c0]     = oacc[mt][nt][2];
            Os[r1 * 68 + c0 + 1] = oacc[mt][nt][3];
        }
    }
    __syncthreads();
#pragma unroll
    for (int j = 0; j < 4; j++) {
        int idx = tid + j * 512;
        int r = idx >> 4, c = (idx & 15) * 4;
        float4 v;
        v.x = Os[r * 68 + c];
        v.y = Os[r * 68 + c + 1];
        v.z = Os[r * 68 + c + 2];
        v.w = Os[r * 68 + c + 3];
        *(float4*)(g_o + headbase + (size_t)(q0 + r) * DH + c) = v;
    }
}

// ============================================================
// Normalize attn rows: attn[row, :] *= 1/Z
// ============================================================
__global__ __launch_bounds__(256) void norm_attn_kernel(float* __restrict__ attn)
{
    int a = blockIdx.x;                 // 0 .. 16*4096-1
    int hb = a >> 12;                   // h*BB + b
    int q  = a & 4095;
    int h = hb >> 1, b = hb & 1;
    float zi = g_zi[(size_t)(b * HH + h) * NQ + q];
    float4* row = (float4*)(attn + (size_t)a * NK);
    int i = threadIdx.x;
#pragma unroll
    for (int j = 0; j < 4; j++) {
        float4 v = row[i + j * 256];
        v.x *= zi; v.y *= zi; v.z *= zi; v.w *= zi;
        row[i + j * 256] = v;
    }
}

// ============================================================
extern "C" void kernel_launch(void* const* d_in, const int* in_sizes, int n_in,
                              void* d_out, int out_size)
{
    const float* q  = (const float*)d_in[0];
    const float* k  = (const float*)d_in[1];
    const float* v  = (const float*)d_in[2];
    const unsigned char* mask = (const unsigned char*)d_in[3];
    const float* Wq = (const float*)d_in[4];
    const float* bq = (const float*)d_in[5];
    const float* Wk = (const float*)d_in[6];
    const float* bk = (const float*)d_in[7];
    const float* Wv = (const float*)d_in[8];
    const float* bv = (const float*)d_in[9];
    const float* Wo = (const float*)d_in[10];
    const float* bo = (const float*)d_in[11];

    float* out  = (float*)d_out;
    float* attn = out;                                    // [16, 4096, 4096]
    float* outp = out + (size_t)HH * BB * NQ * NK;        // [2, 4096, 512]

    proj_head_kernel<<<dim3(64, 8), 256>>>(q, Wq, bq, 0);
    proj_head_kernel<<<dim3(64, 8), 256>>>(k, Wk, bk, 1);
    proj_head_kernel<<<dim3(64, 8), 256>>>(v, Wv, bv, 2);

    cudaFuncSetAttribute(attn_kernel, cudaFuncAttributeMaxDynamicSharedMemorySize, SMEM_BYTES);
    attn_kernel<<<dim3(NQ / 128, BB * HH), 512, SMEM_BYTES>>>(mask, attn);

    norm_attn_kernel<<<dim3(HH * BB * NQ), 256>>>(attn);

    proj_out_kernel<<<dim3(64, 8), 256>>>(Wo, bo, outp);
}

// round 4
// speedup vs baseline: 1.5385x; 1.5385x over previous
#include <cuda_runtime.h>
#include <cuda_fp16.h>
#include <cstdint>

#define BB 2
#define HH 8
#define DH 64
#define DM 512
#define NQ 4096
#define NK 4096

// -------- scratch (no allocations allowed) --------
__device__ float g_qh[BB*HH*NQ*DH];
__device__ float g_kh[BB*HH*NK*DH];
__device__ float g_vh[BB*HH*NK*DH];
__device__ float g_o [BB*HH*NQ*DH];   // UNNORMALIZED O (E @ V)
__device__ float g_zi[BB*HH*NQ];      // 1 / rowsum(exp(S))

__device__ __forceinline__ float to_tf32(float x) {
    float r;
    asm("cvt.rna.tf32.f32 %0, %1;" : "=f"(r) : "f"(x));
    return r;
}

// tf32: D += A(16x8) * B(8x8)
__device__ __forceinline__ void mma8(float* d, const float* a, const float* b) {
    asm("mma.sync.aligned.m16n8k8.row.col.f32.tf32.tf32.f32 "
        "{%0,%1,%2,%3}, {%4,%5,%6,%7}, {%8,%9}, {%0,%1,%2,%3};"
        : "+f"(d[0]), "+f"(d[1]), "+f"(d[2]), "+f"(d[3])
        : "r"(__float_as_uint(a[0])), "r"(__float_as_uint(a[1])),
          "r"(__float_as_uint(a[2])), "r"(__float_as_uint(a[3])),
          "r"(__float_as_uint(b[0])), "r"(__float_as_uint(b[1])));
}

// fp16: D(16x8,f32) += A(16x16) * B(16x8), packed half2 operands
__device__ __forceinline__ void mma16(float* d, const uint32_t* a, const uint32_t* b) {
    asm("mma.sync.aligned.m16n8k16.row.col.f32.f16.f16.f32 "
        "{%0,%1,%2,%3}, {%4,%5,%6,%7}, {%8,%9}, {%0,%1,%2,%3};"
        : "+f"(d[0]), "+f"(d[1]), "+f"(d[2]), "+f"(d[3])
        : "r"(a[0]), "r"(a[1]), "r"(a[2]), "r"(a[3]),
          "r"(b[0]), "r"(b[1]));
}

__device__ __forceinline__ uint32_t pack_h2(float x, float y) {
    __half2 h = __floats2half2_rn(x, y);
    return *(uint32_t*)&h;
}

// ============================================================
// QKV projection (tf32): Y[b,h,n,d] = X @ W^T + bias, head-major scatter.
// ============================================================
__global__ __launch_bounds__(256) void proj_head_kernel(
    const float* __restrict__ X, const float* __restrict__ W,
    const float* __restrict__ bias, int sel)
{
    float* dst = sel == 0 ? g_qh : (sel == 1 ? g_kh : g_vh);
    __shared__ float As[128][36];
    __shared__ float Ws[64][36];
    int tid = threadIdx.x;
    int lane = tid & 31, warp = tid >> 5;
    int g = lane >> 2, t = lane & 3;
    int wm = warp >> 1, wn = warp & 1;
    int m0 = blockIdx.x * 128;
    int h  = blockIdx.y;

    float acc[2][4][4];
#pragma unroll
    for (int i = 0; i < 2; i++)
#pragma unroll
        for (int j = 0; j < 4; j++)
#pragma unroll
            for (int c = 0; c < 4; c++) acc[i][j][c] = 0.f;

    int rl = tid >> 3, cl = (tid & 7) * 4;
    for (int k0 = 0; k0 < DM; k0 += 32) {
#pragma unroll
        for (int i = 0; i < 4; i++) {
            int r = rl + i * 32;
            float4 v = *(const float4*)(X + (size_t)(m0 + r) * DM + k0 + cl);
            As[r][cl]   = to_tf32(v.x);
            As[r][cl+1] = to_tf32(v.y);
            As[r][cl+2] = to_tf32(v.z);
            As[r][cl+3] = to_tf32(v.w);
        }
#pragma unroll
        for (int i = 0; i < 2; i++) {
            int r = rl + i * 32;
            float4 v = *(const float4*)(W + (size_t)(h * 64 + r) * DM + k0 + cl);
            Ws[r][cl]   = to_tf32(v.x);
            Ws[r][cl+1] = to_tf32(v.y);
            Ws[r][cl+2] = to_tf32(v.z);
            Ws[r][cl+3] = to_tf32(v.w);
        }
        __syncthreads();
#pragma unroll
        for (int kk = 0; kk < 4; kk++) {
            float a[2][4];
#pragma unroll
            for (int mt = 0; mt < 2; mt++) {
                int rb = wm * 32 + mt * 16;
                a[mt][0] = As[rb + g][kk*8 + t];
                a[mt][1] = As[rb + 8 + g][kk*8 + t];
                a[mt][2] = As[rb + g][kk*8 + t + 4];
                a[mt][3] = As[rb + 8 + g][kk*8 + t + 4];
            }
            float bf[4][2];
#pragma unroll
            for (int nt = 0; nt < 4; nt++) {
                int nl = wn * 32 + nt * 8 + g;
                bf[nt][0] = Ws[nl][kk*8 + t];
                bf[nt][1] = Ws[nl][kk*8 + t + 4];
            }
#pragma unroll
            for (int mt = 0; mt < 2; mt++)
#pragma unroll
                for (int nt = 0; nt < 4; nt++)
                    mma8(acc[mt][nt], a[mt], bf[nt]);
        }
        __syncthreads();
    }
#pragma unroll
    for (int mt = 0; mt < 2; mt++) {
        int r0 = m0 + wm * 32 + mt * 16 + g;
        int r1 = r0 + 8;
#pragma unroll
        for (int nt = 0; nt < 4; nt++) {
            int col = wn * 32 + nt * 8 + 2 * t;
            float b0v = bias[h * 64 + col], b1v = bias[h * 64 + col + 1];
            int b_ = r0 >> 12, q_ = r0 & 4095;
            float* p = dst + (size_t)((b_ * HH + h) * NQ + q_) * DH + col;
            p[0] = acc[mt][nt][0] + b0v;
            p[1] = acc[mt][nt][1] + b1v;
            b_ = r1 >> 12; q_ = r1 & 4095;
            p = dst + (size_t)((b_ * HH + h) * NQ + q_) * DH + col;
            p[0] = acc[mt][nt][2] + b0v;
            p[1] = acc[mt][nt][3] + b1v;
        }
    }
}

// ============================================================
// Output projection (tf32): output = (concat_heads(g_o) * invZ) @ Wo^T + bo
// ============================================================
__global__ __launch_bounds__(256) void proj_out_kernel(
    const float* __restrict__ W, const float* __restrict__ bias,
    float* __restrict__ Y)
{
    __shared__ float As[128][36];
    __shared__ float Ws[64][36];
    int tid = threadIdx.x;
    int lane = tid & 31, warp = tid >> 5;
    int g = lane >> 2, t = lane & 3;
    int wm = warp >> 1, wn = warp & 1;
    int m0 = blockIdx.x * 128;
    int n0 = blockIdx.y * 64;

    float acc[2][4][4];
#pragma unroll
    for (int i = 0; i < 2; i++)
#pragma unroll
        for (int j = 0; j < 4; j++)
#pragma unroll
            for (int c = 0; c < 4; c++) acc[i][j][c] = 0.f;

    int rl = tid >> 3, cl = (tid & 7) * 4;
    for (int k0 = 0; k0 < DM; k0 += 32) {
        int head = k0 >> 6;
        int dd = (k0 & 63) + cl;
#pragma unroll
        for (int i = 0; i < 4; i++) {
            int r = rl + i * 32;
            int row = m0 + r;
            int b_ = row >> 12, q_ = row & 4095;
            size_t hb = (size_t)(b_ * HH + head) * NQ + q_;
            float zi = g_zi[hb];
            float4 v = *(const float4*)(g_o + hb * DH + dd);
            As[r][cl]   = to_tf32(v.x * zi);
            As[r][cl+1] = to_tf32(v.y * zi);
            As[r][cl+2] = to_tf32(v.z * zi);
            As[r][cl+3] = to_tf32(v.w * zi);
        }
#pragma unroll
        for (int i = 0; i < 2; i++) {
            int r = rl + i * 32;
            float4 v = *(const float4*)(W + (size_t)(n0 + r) * DM + k0 + cl);
            Ws[r][cl]   = to_tf32(v.x);
            Ws[r][cl+1] = to_tf32(v.y);
            Ws[r][cl+2] = to_tf32(v.z);
            Ws[r][cl+3] = to_tf32(v.w);
        }
        __syncthreads();
#pragma unroll
        for (int kk = 0; kk < 4; kk++) {
            float a[2][4];
#pragma unroll
            for (int mt = 0; mt < 2; mt++) {
                int rb = wm * 32 + mt * 16;
                a[mt][0] = As[rb + g][kk*8 + t];
                a[mt][1] = As[rb + 8 + g][kk*8 + t];
                a[mt][2] = As[rb + g][kk*8 + t + 4];
                a[mt][3] = As[rb + 8 + g][kk*8 + t + 4];
            }
            float bf[4][2];
#pragma unroll
            for (int nt = 0; nt < 4; nt++) {
                int nl = wn * 32 + nt * 8 + g;
                bf[nt][0] = Ws[nl][kk*8 + t];
                bf[nt][1] = Ws[nl][kk*8 + t + 4];
            }
#pragma unroll
            for (int mt = 0; mt < 2; mt++)
#pragma unroll
                for (int nt = 0; nt < 4; nt++)
                    mma8(acc[mt][nt], a[mt], bf[nt]);
        }
        __syncthreads();
    }
#pragma unroll
    for (int mt = 0; mt < 2; mt++) {
        int r0 = m0 + wm * 32 + mt * 16 + g;
        int r1 = r0 + 8;
#pragma unroll
        for (int nt = 0; nt < 4; nt++) {
            int col = wn * 32 + nt * 8 + 2 * t;
            float b0v = bias[n0 + col], b1v = bias[n0 + col + 1];
            float* p = Y + (size_t)r0 * DM + n0 + col;
            p[0] = acc[mt][nt][0] + b0v;
            p[1] = acc[mt][nt][1] + b1v;
            p = Y + (size_t)r1 * DM + n0 + col;
            p[0] = acc[mt][nt][2] + b0v;
            p[1] = acc[mt][nt][3] + b1v;
        }
    }
}

// ============================================================
// Attention, fp16 mma (m16n8k16), single pass, 256 thr, 64-row Q tile.
// S phase: 8 warps = 2(wm)x4(wn), warp tile 32x32 over 64x128 S.
// AV phase: warp (wm,wn) owns rows wm*32..+32, cols wn*16..+16 (disjoint).
// E written unnormalized (fp32); Z accumulated; O unnormalized to g_o.
// ============================================================
// half-element offsets inside dynamic smem (measured in bytes at the end)
#define QH_OFF   0                     // half [64][72]   =  9216 B
#define KH_OFF   9216                  // half [128][72]  = 18432 B
#define VT_OFF   27648                 // half [64][136]  = 17408 B  (n-major, k contig)
#define PSF_OFF  45056                 // float [64][132] = 33792 B
#define PH_OFF   78848                 // half [64][136]  = 17408 B
#define ZS_OFF   96256                 // float [64]      =   256 B
#define MS_OFF   96512                 // u32 [64][32]    =  8192 B
#define SMEM_BYTES 104704

__global__ __launch_bounds__(256, 2) void attn_kernel(
    const unsigned char* __restrict__ mask, float* __restrict__ attn)
{
    extern __shared__ char smraw[];
    __half* Qh = (__half*)(smraw + QH_OFF);
    __half* Kh = (__half*)(smraw + KH_OFF);
    __half* Vt = (__half*)(smraw + VT_OFF);
    float*  Psf = (float*)(smraw + PSF_OFF);
    __half* Ph = (__half*)(smraw + PH_OFF);
    float*  Zs  = (float*)(smraw + ZS_OFF);
    unsigned int* Ms = (unsigned int*)(smraw + MS_OFF);
    const uint32_t* Qw = (const uint32_t*)Qh;   // word view (2 halfs)
    const uint32_t* Kw = (const uint32_t*)Kh;
    const uint32_t* Vw = (const uint32_t*)Vt;
    const uint32_t* Pw = (const uint32_t*)Ph;
    uint32_t* Phw = (uint32_t*)Ph;

    int tid = threadIdx.x;
    int lane = tid & 31, warp = tid >> 5;
    int g = lane >> 2, t = lane & 3;
    int wm = warp >> 2;   // 0..1
    int wn = warp & 3;    // 0..3
    int q0 = blockIdx.x * 64;
    int bh = blockIdx.y;
    int b = bh >> 3, h = bh & 7;
    size_t headbase = (size_t)(b * HH + h) * NQ * DH;
    const unsigned char* mbase = mask + (size_t)(b * NQ + q0) * NK;
    int rbase = wm * 32;

    // ---- load Q tile as half, pre-scaled by 1/8 ----
#pragma unroll
    for (int j = 0; j < 4; j++) {
        int idx = tid + j * 256;
        int r = idx >> 4, c = (idx & 15) * 4;
        float4 v = *(const float4*)(g_qh + headbase + (size_t)(q0 + r) * DH + c);
        uint32_t* dst = (uint32_t*)(Qh + r * 72 + c);
        dst[0] = pack_h2(v.x * 0.125f, v.y * 0.125f);
        dst[1] = pack_h2(v.z * 0.125f, v.w * 0.125f);
    }
    if (tid < 64) Zs[tid] = 0.f;

    float oacc[2][2][4];
#pragma unroll
    for (int i = 0; i < 2; i++)
#pragma unroll
        for (int j = 0; j < 2; j++)
#pragma unroll
            for (int c = 0; c < 4; c++) oacc[i][j][c] = 0.f;

    for (int kt = 0; kt < NK / 128; kt++) {
        int k0 = kt * 128;
        __syncthreads();
        // ---- load K tile [128][64] as half (k-major rows) ----
#pragma unroll
        for (int j = 0; j < 8; j++) {
            int idx = tid + j * 256;
            int r = idx >> 4, c = (idx & 15) * 4;
            float4 v = *(const float4*)(g_kh + headbase + (size_t)(k0 + r) * DH + c);
            uint32_t* dst = (uint32_t*)(Kh + r * 72 + c);
            dst[0] = pack_h2(v.x, v.y);
            dst[1] = pack_h2(v.z, v.w);
        }
        // ---- load V tile transposed -> Vt[n][k] (n=0..63, k=0..127) ----
#pragma unroll
        for (int j = 0; j < 8; j++) {
            int idx = tid + j * 256;
            int r = idx >> 4, c = (idx & 15) * 4;    // r = k index, c = n index
            float4 v = *(const float4*)(g_vh + headbase + (size_t)(k0 + r) * DH + c);
            Vt[(c    ) * 136 + r] = __float2half_rn(v.x);
            Vt[(c + 1) * 136 + r] = __float2half_rn(v.y);
            Vt[(c + 2) * 136 + r] = __float2half_rn(v.z);
            Vt[(c + 3) * 136 + r] = __float2half_rn(v.w);
        }
        // ---- load mask tile ----
#pragma unroll
        for (int j = 0; j < 8; j++) {
            int idx = tid + j * 256;
            int r = idx >> 5, c = idx & 31;
            Ms[r * 32 + c] = *(const unsigned int*)(mbase + (size_t)r * NK + k0 + c * 4);
        }
        __syncthreads();

        // ---- S = Q K^T (fp16 k16 mma) ----
        float sacc[2][4][4];
#pragma unroll
        for (int i = 0; i < 2; i++)
#pragma unroll
            for (int j = 0; j < 4; j++)
#pragma unroll
                for (int c = 0; c < 4; c++) sacc[i][j][c] = 0.f;
#pragma unroll
        for (int kk = 0; kk < 4; kk++) {          // k16 steps over d=64
            uint32_t a[2][4];
#pragma unroll
            for (int mt = 0; mt < 2; mt++) {
                int rb = rbase + mt * 16;
                int w0 = (rb + g) * 36 + kk * 8 + t;
                int w1 = (rb + 8 + g) * 36 + kk * 8 + t;
                a[mt][0] = Qw[w0];
                a[mt][1] = Qw[w1];
                a[mt][2] = Qw[w0 + 4];
                a[mt][3] = Qw[w1 + 4];
            }
            uint32_t bf[4][2];
#pragma unroll
            for (int nt = 0; nt < 4; nt++) {
                int nl = wn * 32 + nt * 8 + g;
                int w = nl * 36 + kk * 8 + t;
                bf[nt][0] = Kw[w];
                bf[nt][1] = Kw[w + 4];
            }
#pragma unroll
            for (int mt = 0; mt < 2; mt++)
#pragma unroll
                for (int nt = 0; nt < 4; nt++)
                    mma16(sacc[mt][nt], a[mt], bf[nt]);
        }

        // ---- E = exp(S) masked; Z accumulate; stage fp32 + half ----
        const unsigned char* Mb = (const unsigned char*)Ms;
        float rsum[4] = {0.f, 0.f, 0.f, 0.f};
#pragma unroll
        for (int mt = 0; mt < 2; mt++) {
            int r0 = rbase + mt * 16 + g, r1 = r0 + 8;
#pragma unroll
            for (int nt = 0; nt < 4; nt++) {
                int c0 = wn * 32 + nt * 8 + 2 * t;
                float p00 = Mb[r0*128 + c0]     ? 0.f : __expf(sacc[mt][nt][0]);
                float p01 = Mb[r0*128 + c0 + 1] ? 0.f : __expf(sacc[mt][nt][1]);
                float p10 = Mb[r1*128 + c0]     ? 0.f : __expf(sacc[mt][nt][2]);
                float p11 = Mb[r1*128 + c0 + 1] ? 0.f : __expf(sacc[mt][nt][3]);
                rsum[mt*2]     += p00 + p01;
                rsum[mt*2 + 1] += p10 + p11;
                Psf[r0*132 + c0]     = p00;
                Psf[r0*132 + c0 + 1] = p01;
                Psf[r1*132 + c0]     = p10;
                Psf[r1*132 + c0 + 1] = p11;
                Phw[r0*68 + (c0 >> 1)] = pack_h2(p00, p01);
                Phw[r1*68 + (c0 >> 1)] = pack_h2(p10, p11);
            }
        }
#pragma unroll
        for (int i = 0; i < 4; i++) {
            rsum[i] += __shfl_xor_sync(0xffffffffu, rsum[i], 1);
            rsum[i] += __shfl_xor_sync(0xffffffffu, rsum[i], 2);
        }
        if (t == 0) {
            atomicAdd(&Zs[rbase + g],      rsum[0]);
            atomicAdd(&Zs[rbase + 8 + g],  rsum[1]);
            atomicAdd(&Zs[rbase + 16 + g], rsum[2]);
            atomicAdd(&Zs[rbase + 24 + g], rsum[3]);
        }
        __syncthreads();

        // ---- write UNNORMALIZED E tile (attn layout [h*BB+b, q, k]) ----
        size_t abase = ((size_t)(h * BB + b) * NQ + q0) * NK + k0;
#pragma unroll
        for (int j = 0; j < 8; j++) {
            int idx = tid + j * 256;
            int r = idx >> 5, c = (idx & 31) * 4;
            float4 v = *(const float4*)(Psf + r * 132 + c);
            *(float4*)(attn + abase + (size_t)r * NK + c) = v;
        }

        // ---- O += E @ V (fp16): warp rows rbase..+32, cols wn*16..+16 ----
#pragma unroll
        for (int kk = 0; kk < 8; kk++) {          // k16 steps over k=128
            int kw = kk * 8;                      // word offset along k
            uint32_t a[2][4];
#pragma unroll
            for (int mt = 0; mt < 2; mt++) {
                int rb = rbase + mt * 16;
                int w0 = (rb + g) * 68 + kw + t;
                int w1 = (rb + 8 + g) * 68 + kw + t;
                a[mt][0] = Pw[w0];
                a[mt][1] = Pw[w1];
                a[mt][2] = Pw[w0 + 4];
                a[mt][3] = Pw[w1 + 4];
            }
            uint32_t bf[2][2];
#pragma unroll
            for (int nt = 0; nt < 2; nt++) {
                int nc = wn * 16 + nt * 8 + g;
                int w = nc * 68 + kw + t;
                bf[nt][0] = Vw[w];
                bf[nt][1] = Vw[w + 4];
            }
#pragma unroll
            for (int mt = 0; mt < 2; mt++)
#pragma unroll
                for (int nt = 0; nt < 2; nt++)
                    mma16(oacc[mt][nt], a[mt], bf[nt]);
        }
    }

    // ---- write 1/Z ----
    __syncthreads();
    if (tid < 64) {
        g_zi[(size_t)(b * HH + h) * NQ + q0 + tid] = 1.0f / Zs[tid];
    }

    // ---- stage O (disjoint ownership), coalesced write to g_o ----
    float* Os = Psf;   // reuse as [64][68]
#pragma unroll
    for (int mt = 0; mt < 2; mt++) {
        int r0 = rbase + mt * 16 + g, r1 = r0 + 8;
#pragma unroll
        for (int nt = 0; nt < 2; nt++) {
            int c0 = wn * 16 + nt * 8 + 2 * t;
            Os[r0 * 68 + c0]     = oacc[mt][nt][0];
            Os[r0 * 68 + c0 + 1] = oacc[mt][nt][1];
            Os[r1 * 68 + c0]     = oacc[mt][nt][2];
            Os[r1 * 68 + c0 + 1] = oacc[mt][nt][3];
        }
    }
    __syncthreads();
#pragma unroll
    for (int j = 0; j < 4; j++) {
        int idx = tid + j * 256;
        int r = idx >> 4, c = (idx & 15) * 4;
        float4 v;
        v.x = Os[r * 68 + c];
        v.y = Os[r * 68 + c + 1];
        v.z = Os[r * 68 + c + 2];
        v.w = Os[r * 68 + c + 3];
        *(float4*)(g_o + headbase + (size_t)(q0 + r) * DH + c) = v;
    }
}

// ============================================================
// Normalize attn rows: attn[row, :] *= 1/Z
// ============================================================
__global__ __launch_bounds__(256) void norm_attn_kernel(float* __restrict__ attn)
{
    int a = blockIdx.x;                 // 0 .. 16*4096-1
    int hb = a >> 12;                   // h*BB + b
    int q  = a & 4095;
    int h = hb >> 1, b = hb & 1;
    float zi = g_zi[(size_t)(b * HH + h) * NQ + q];
    float4* row = (float4*)(attn + (size_t)a * NK);
    int i = threadIdx.x;
#pragma unroll
    for (int j = 0; j < 4; j++) {
        float4 v = row[i + j * 256];
        v.x *= zi; v.y *= zi; v.z *= zi; v.w *= zi;
        row[i + j * 256] = v;
    }
}

// ============================================================
extern "C" void kernel_launch(void* const* d_in, const int* in_sizes, int n_in,
                              void* d_out, int out_size)
{
    const float* q  = (const float*)d_in[0];
    const float* k  = (const float*)d_in[1];
    const float* v  = (const float*)d_in[2];
    const unsigned char* mask = (const unsigned char*)d_in[3];
    const float* Wq = (const float*)d_in[4];
    const float* bq = (const float*)d_in[5];
    const float* Wk = (const float*)d_in[6];
    const float* bk = (const float*)d_in[7];
    const float* Wv = (const float*)d_in[8];
    const float* bv = (const float*)d_in[9];
    const float* Wo = (const float*)d_in[10];
    const float* bo = (const float*)d_in[11];

    float* out  = (float*)d_out;
    float* attn = out;                                    // [16, 4096, 4096]
    float* outp = out + (size_t)HH * BB * NQ * NK;        // [2, 4096, 512]

    proj_head_kernel<<<dim3(64, 8), 256>>>(q, Wq, bq, 0);
    proj_head_kernel<<<dim3(64, 8), 256>>>(k, Wk, bk, 1);
    proj_head_kernel<<<dim3(64, 8), 256>>>(v, Wv, bv, 2);

    cudaFuncSetAttribute(attn_kernel, cudaFuncAttributeMaxDynamicSharedMemorySize, SMEM_BYTES);
    attn_kernel<<<dim3(NQ / 64, BB * HH), 256, SMEM_BYTES>>>(mask, attn);

    norm_attn_kernel<<<dim3(HH * BB * NQ), 256>>>(attn);

    proj_out_kernel<<<dim3(64, 8), 256>>>(Wo, bo, outp);
}

// round 5
// speedup vs baseline: 2.2541x; 1.4651x over previous
#include <cuda_runtime.h>
#include <cuda_fp16.h>
#include <cstdint>

#define BB 2
#define HH 8
#define DH 64
#define DM 512
#define NQ 4096
#define NK 4096

// -------- scratch (no allocations allowed) --------
__device__ float g_qh[BB*HH*NQ*DH];
__device__ float g_kh[BB*HH*NK*DH];
__device__ float g_vh[BB*HH*NK*DH];
__device__ float g_o [BB*HH*NQ*DH];   // UNNORMALIZED O (E @ V)
__device__ float g_zi[BB*HH*NQ];      // 1 / rowsum(exp(S))

__device__ __forceinline__ float to_tf32(float x) {
    float r;
    asm("cvt.rna.tf32.f32 %0, %1;" : "=f"(r) : "f"(x));
    return r;
}

// tf32: D += A(16x8) * B(8x8)
__device__ __forceinline__ void mma8(float* d, const float* a, const float* b) {
    asm("mma.sync.aligned.m16n8k8.row.col.f32.tf32.tf32.f32 "
        "{%0,%1,%2,%3}, {%4,%5,%6,%7}, {%8,%9}, {%0,%1,%2,%3};"
        : "+f"(d[0]), "+f"(d[1]), "+f"(d[2]), "+f"(d[3])
        : "r"(__float_as_uint(a[0])), "r"(__float_as_uint(a[1])),
          "r"(__float_as_uint(a[2])), "r"(__float_as_uint(a[3])),
          "r"(__float_as_uint(b[0])), "r"(__float_as_uint(b[1])));
}

// fp16: D(16x8,f32) += A(16x16) * B(16x8), packed half2 operands
__device__ __forceinline__ void mma16(float* d, const uint32_t* a, const uint32_t* b) {
    asm("mma.sync.aligned.m16n8k16.row.col.f32.f16.f16.f32 "
        "{%0,%1,%2,%3}, {%4,%5,%6,%7}, {%8,%9}, {%0,%1,%2,%3};"
        : "+f"(d[0]), "+f"(d[1]), "+f"(d[2]), "+f"(d[3])
        : "r"(a[0]), "r"(a[1]), "r"(a[2]), "r"(a[3]),
          "r"(b[0]), "r"(b[1]));
}

__device__ __forceinline__ void ldsm_x4(uint32_t* r, uint32_t addr) {
    asm volatile("ldmatrix.sync.aligned.m8n8.x4.shared.b16 {%0,%1,%2,%3}, [%4];"
        : "=r"(r[0]), "=r"(r[1]), "=r"(r[2]), "=r"(r[3]) : "r"(addr));
}
__device__ __forceinline__ void ldsm_x4_t(uint32_t* r, uint32_t addr) {
    asm volatile("ldmatrix.sync.aligned.m8n8.x4.trans.shared.b16 {%0,%1,%2,%3}, [%4];"
        : "=r"(r[0]), "=r"(r[1]), "=r"(r[2]), "=r"(r[3]) : "r"(addr));
}

__device__ __forceinline__ uint32_t pack_h2(float x, float y) {
    __half2 h = __floats2half2_rn(x, y);
    return *(uint32_t*)&h;
}
__device__ __forceinline__ uint32_t smem_u32(const void* p) {
    return (uint32_t)__cvta_generic_to_shared(p);
}

// ============================================================
// QKV projection (tf32): Y[b,h,n,d] = X @ W^T + bias, head-major scatter.
// ============================================================
__global__ __launch_bounds__(256) void proj_head_kernel(
    const float* __restrict__ X, const float* __restrict__ W,
    const float* __restrict__ bias, int sel)
{
    float* dst = sel == 0 ? g_qh : (sel == 1 ? g_kh : g_vh);
    __shared__ float As[128][36];
    __shared__ float Ws[64][36];
    int tid = threadIdx.x;
    int lane = tid & 31, warp = tid >> 5;
    int g = lane >> 2, t = lane & 3;
    int wm = warp >> 1, wn = warp & 1;
    int m0 = blockIdx.x * 128;
    int h  = blockIdx.y;

    float acc[2][4][4];
#pragma unroll
    for (int i = 0; i < 2; i++)
#pragma unroll
        for (int j = 0; j < 4; j++)
#pragma unroll
            for (int c = 0; c < 4; c++) acc[i][j][c] = 0.f;

    int rl = tid >> 3, cl = (tid & 7) * 4;
    for (int k0 = 0; k0 < DM; k0 += 32) {
#pragma unroll
        for (int i = 0; i < 4; i++) {
            int r = rl + i * 32;
            float4 v = *(const float4*)(X + (size_t)(m0 + r) * DM + k0 + cl);
            As[r][cl]   = to_tf32(v.x);
            As[r][cl+1] = to_tf32(v.y);
            As[r][cl+2] = to_tf32(v.z);
            As[r][cl+3] = to_tf32(v.w);
        }
#pragma unroll
        for (int i = 0; i < 2; i++) {
            int r = rl + i * 32;
            float4 v = *(const float4*)(W + (size_t)(h * 64 + r) * DM + k0 + cl);
            Ws[r][cl]   = to_tf32(v.x);
            Ws[r][cl+1] = to_tf32(v.y);
            Ws[r][cl+2] = to_tf32(v.z);
            Ws[r][cl+3] = to_tf32(v.w);
        }
        __syncthreads();
#pragma unroll
        for (int kk = 0; kk < 4; kk++) {
            float a[2][4];
#pragma unroll
            for (int mt = 0; mt < 2; mt++) {
                int rb = wm * 32 + mt * 16;
                a[mt][0] = As[rb + g][kk*8 + t];
                a[mt][1] = As[rb + 8 + g][kk*8 + t];
                a[mt][2] = As[rb + g][kk*8 + t + 4];
                a[mt][3] = As[rb + 8 + g][kk*8 + t + 4];
            }
            float bf[4][2];
#pragma unroll
            for (int nt = 0; nt < 4; nt++) {
                int nl = wn * 32 + nt * 8 + g;
                bf[nt][0] = Ws[nl][kk*8 + t];
                bf[nt][1] = Ws[nl][kk*8 + t + 4];
            }
#pragma unroll
            for (int mt = 0; mt < 2; mt++)
#pragma unroll
                for (int nt = 0; nt < 4; nt++)
                    mma8(acc[mt][nt], a[mt], bf[nt]);
        }
        __syncthreads();
    }
#pragma unroll
    for (int mt = 0; mt < 2; mt++) {
        int r0 = m0 + wm * 32 + mt * 16 + g;
        int r1 = r0 + 8;
#pragma unroll
        for (int nt = 0; nt < 4; nt++) {
            int col = wn * 32 + nt * 8 + 2 * t;
            float b0v = bias[h * 64 + col], b1v = bias[h * 64 + col + 1];
            int b_ = r0 >> 12, q_ = r0 & 4095;
            float* p = dst + (size_t)((b_ * HH + h) * NQ + q_) * DH + col;
            p[0] = acc[mt][nt][0] + b0v;
            p[1] = acc[mt][nt][1] + b1v;
            b_ = r1 >> 12; q_ = r1 & 4095;
            p = dst + (size_t)((b_ * HH + h) * NQ + q_) * DH + col;
            p[0] = acc[mt][nt][2] + b0v;
            p[1] = acc[mt][nt][3] + b1v;
        }
    }
}

// ============================================================
// Output projection (tf32): output = (concat_heads(g_o) * invZ) @ Wo^T + bo
// ============================================================
__global__ __launch_bounds__(256) void proj_out_kernel(
    const float* __restrict__ W, const float* __restrict__ bias,
    float* __restrict__ Y)
{
    __shared__ float As[128][36];
    __shared__ float Ws[64][36];
    int tid = threadIdx.x;
    int lane = tid & 31, warp = tid >> 5;
    int g = lane >> 2, t = lane & 3;
    int wm = warp >> 1, wn = warp & 1;
    int m0 = blockIdx.x * 128;
    int n0 = blockIdx.y * 64;

    float acc[2][4][4];
#pragma unroll
    for (int i = 0; i < 2; i++)
#pragma unroll
        for (int j = 0; j < 4; j++)
#pragma unroll
            for (int c = 0; c < 4; c++) acc[i][j][c] = 0.f;

    int rl = tid >> 3, cl = (tid & 7) * 4;
    for (int k0 = 0; k0 < DM; k0 += 32) {
        int head = k0 >> 6;
        int dd = (k0 & 63) + cl;
#pragma unroll
        for (int i = 0; i < 4; i++) {
            int r = rl + i * 32;
            int row = m0 + r;
            int b_ = row >> 12, q_ = row & 4095;
            size_t hb = (size_t)(b_ * HH + head) * NQ + q_;
            float zi = g_zi[hb];
            float4 v = *(const float4*)(g_o + hb * DH + dd);
            As[r][cl]   = to_tf32(v.x * zi);
            As[r][cl+1] = to_tf32(v.y * zi);
            As[r][cl+2] = to_tf32(v.z * zi);
            As[r][cl+3] = to_tf32(v.w * zi);
        }
#pragma unroll
        for (int i = 0; i < 2; i++) {
            int r = rl + i * 32;
            float4 v = *(const float4*)(W + (size_t)(n0 + r) * DM + k0 + cl);
            Ws[r][cl]   = to_tf32(v.x);
            Ws[r][cl+1] = to_tf32(v.y);
            Ws[r][cl+2] = to_tf32(v.z);
            Ws[r][cl+3] = to_tf32(v.w);
        }
        __syncthreads();
#pragma unroll
        for (int kk = 0; kk < 4; kk++) {
            float a[2][4];
#pragma unroll
            for (int mt = 0; mt < 2; mt++) {
                int rb = wm * 32 + mt * 16;
                a[mt][0] = As[rb + g][kk*8 + t];
                a[mt][1] = As[rb + 8 + g][kk*8 + t];
                a[mt][2] = As[rb + g][kk*8 + t + 4];
                a[mt][3] = As[rb + 8 + g][kk*8 + t + 4];
            }
            float bf[4][2];
#pragma unroll
            for (int nt = 0; nt < 4; nt++) {
                int nl = wn * 32 + nt * 8 + g;
                bf[nt][0] = Ws[nl][kk*8 + t];
                bf[nt][1] = Ws[nl][kk*8 + t + 4];
            }
#pragma unroll
            for (int mt = 0; mt < 2; mt++)
#pragma unroll
                for (int nt = 0; nt < 4; nt++)
                    mma8(acc[mt][nt], a[mt], bf[nt]);
        }
        __syncthreads();
    }
#pragma unroll
    for (int mt = 0; mt < 2; mt++) {
        int r0 = m0 + wm * 32 + mt * 16 + g;
        int r1 = r0 + 8;
#pragma unroll
        for (int nt = 0; nt < 4; nt++) {
            int col = wn * 32 + nt * 8 + 2 * t;
            float b0v = bias[n0 + col], b1v = bias[n0 + col + 1];
            float* p = Y + (size_t)r0 * DM + n0 + col;
            p[0] = acc[mt][nt][0] + b0v;
            p[1] = acc[mt][nt][1] + b1v;
            p = Y + (size_t)r1 * DM + n0 + col;
            p[0] = acc[mt][nt][2] + b0v;
            p[1] = acc[mt][nt][3] + b1v;
        }
    }
}

// ============================================================
// Attention, fp16 mma + ldmatrix. 256 thr, 64-row Q tile, k-tile 128.
// S: 8 warps = 2(wm)x4(wn) of 32x32.  AV: warp owns rows wm*32..+32,
// cols wn*16..+16 (disjoint).  E staged fp16 only; gmem E written fp32
// from Ph.  Mask fast path via per-tile zero flag (ping-pong).
// ============================================================
// byte offsets in dynamic smem
#define QH_OFF   0                     // half [64][72]   =  9216
#define KH_OFF   9216                  // half [128][72]  = 18432
#define VH_OFF   27648                 // half [128][72]  = 18432  (natural [k][n])
#define PH_OFF   46080                 // half [64][136]  = 17408  (reused as float Os[64][68])
#define ZS_OFF   63488                 // float [64]      =   256
#define MS_OFF   63744                 // u32 [64][32]    =  8192
#define FL_OFF   71936                 // u32 [2] flags   +pad
#define SMEM_BYTES 72064

#define QROW 72
#define KROW 72
#define VROW 72
#define PROW 136

__global__ __launch_bounds__(256, 2) void attn_kernel(
    const unsigned char* __restrict__ mask, float* __restrict__ attn)
{
    extern __shared__ char smraw[];
    __half* Qh = (__half*)(smraw + QH_OFF);
    __half* Kh = (__half*)(smraw + KH_OFF);
    __half* Vh = (__half*)(smraw + VH_OFF);
    __half* Ph = (__half*)(smraw + PH_OFF);
    float*  Zs = (float*)(smraw + ZS_OFF);
    unsigned int* Ms = (unsigned int*)(smraw + MS_OFF);
    unsigned int* Fl = (unsigned int*)(smraw + FL_OFF);
    uint32_t* Phw = (uint32_t*)Ph;

    int tid = threadIdx.x;
    int lane = tid & 31, warp = tid >> 5;
    int g = lane >> 2, t = lane & 3;
    int wm = warp >> 2;   // 0..1
    int wn = warp & 3;    // 0..3
    int q0 = blockIdx.x * 64;
    int bh = blockIdx.y;
    int b = bh >> 3, h = bh & 7;
    size_t headbase = (size_t)(b * HH + h) * NQ * DH;
    const unsigned char* mbase = mask + (size_t)(b * NQ + q0) * NK;
    int rbase = wm * 32;

    uint32_t qbase = smem_u32(Qh);
    uint32_t kbase = smem_u32(Kh);
    uint32_t vbase = smem_u32(Vh);
    uint32_t pbase = smem_u32(Ph);

    // ---- load Q tile as half, pre-scaled by 1/8 ----
#pragma unroll
    for (int j = 0; j < 4; j++) {
        int idx = tid + j * 256;
        int r = idx >> 4, c = (idx & 15) * 4;
        float4 v = *(const float4*)(g_qh + headbase + (size_t)(q0 + r) * DH + c);
        uint2 w;
        w.x = pack_h2(v.x * 0.125f, v.y * 0.125f);
        w.y = pack_h2(v.z * 0.125f, v.w * 0.125f);
        *(uint2*)(Qh + r * QROW + c) = w;
    }
    if (tid < 64) Zs[tid] = 0.f;
    if (tid < 2) Fl[tid] = 0u;
    __syncthreads();

    // ---- hoist Q A-fragments: qa[mt][kk][4] ----
    // lane: row = rbase + mt*16 + ((lane>>3)&1)*8 + (lane&7); col = kk*16 + (lane>>4)*8
    uint32_t qa[2][4][4];
    {
        int qrow = ((lane >> 3) & 1) * 8 + (lane & 7);
        int qcol = (lane >> 4) * 8;
#pragma unroll
        for (int mt = 0; mt < 2; mt++)
#pragma unroll
            for (int kk = 0; kk < 4; kk++)
                ldsm_x4(qa[mt][kk],
                        qbase + ((rbase + mt * 16 + qrow) * QROW + kk * 16 + qcol) * 2);
    }

    float oacc[2][2][4];
#pragma unroll
    for (int i = 0; i < 2; i++)
#pragma unroll
        for (int j = 0; j < 2; j++)
#pragma unroll
            for (int c = 0; c < 4; c++) oacc[i][j][c] = 0.f;

    for (int kt = 0; kt < NK / 128; kt++) {
        int k0 = kt * 128;
        __syncthreads();
        // ---- load K and V tiles as half (natural [k-row][d] / [k][n]) ----
#pragma unroll
        for (int j = 0; j < 8; j++) {
            int idx = tid + j * 256;
            int r = idx >> 4, c = (idx & 15) * 4;
            float4 v = *(const float4*)(g_kh + headbase + (size_t)(k0 + r) * DH + c);
            uint2 w;
            w.x = pack_h2(v.x, v.y);
            w.y = pack_h2(v.z, v.w);
            *(uint2*)(Kh + r * KROW + c) = w;
            float4 u = *(const float4*)(g_vh + headbase + (size_t)(k0 + r) * DH + c);
            uint2 w2;
            w2.x = pack_h2(u.x, u.y);
            w2.y = pack_h2(u.z, u.w);
            *(uint2*)(Vh + r * VROW + c) = w2;
        }
        // ---- load mask tile + zero-flag (ping-pong flag kt&1) ----
        {
            int r = tid >> 2, cb = (tid & 3) * 8;   // 8 words = 32 bytes per thread
            const uint4* src = (const uint4*)(mbase + (size_t)r * NK + k0 + cb * 4);
            uint4 m0 = src[0], m1 = src[1];
            *(uint4*)(Ms + r * 32 + cb)     = m0;
            *(uint4*)(Ms + r * 32 + cb + 4) = m1;
            unsigned int orv = m0.x | m0.y | m0.z | m0.w | m1.x | m1.y | m1.z | m1.w;
            if (orv) atomicOr(&Fl[kt & 1], 1u);
        }
        __syncthreads();
        unsigned int mflag = Fl[kt & 1];
        if (tid == 0) Fl[(kt & 1) ^ 1] = 0u;   // reset other flag for next tile

        // ---- S = Q K^T via ldmatrix + fp16 mma ----
        float sacc[2][4][4];
#pragma unroll
        for (int i = 0; i < 2; i++)
#pragma unroll
            for (int j = 0; j < 4; j++)
#pragma unroll
                for (int c = 0; c < 4; c++) sacc[i][j][c] = 0.f;
        {
            // K B-frag lane addressing: n = wn*32 + (lane>>4)*8 + (lane&7), k = kk*16 + ((lane>>3)&1)*8
            int kn = (lane >> 4) * 8 + (lane & 7);
            int kc = ((lane >> 3) & 1) * 8;
#pragma unroll
            for (int kk = 0; kk < 4; kk++) {
                uint32_t bf[4][2];
#pragma unroll
                for (int half_n = 0; half_n < 2; half_n++) {
                    uint32_t r4[4];
                    ldsm_x4(r4, kbase + ((wn * 32 + half_n * 16 + kn) * KROW + kk * 16 + kc) * 2);
                    bf[half_n * 2][0]     = r4[0];
                    bf[half_n * 2][1]     = r4[1];
                    bf[half_n * 2 + 1][0] = r4[2];
                    bf[half_n * 2 + 1][1] = r4[3];
                }
#pragma unroll
                for (int mt = 0; mt < 2; mt++)
#pragma unroll
                    for (int nt = 0; nt < 4; nt++)
                        mma16(sacc[mt][nt], qa[mt][kk], bf[nt]);
            }
        }

        // ---- E = exp(S) (mask fast/slow path); Z accumulate; stage fp16 ----
        float rsum[4] = {0.f, 0.f, 0.f, 0.f};
        if (!mflag) {
#pragma unroll
            for (int mt = 0; mt < 2; mt++) {
                int r0 = rbase + mt * 16 + g, r1 = r0 + 8;
#pragma unroll
                for (int nt = 0; nt < 4; nt++) {
                    int c0 = wn * 32 + nt * 8 + 2 * t;
                    float p00 = __expf(sacc[mt][nt][0]);
                    float p01 = __expf(sacc[mt][nt][1]);
                    float p10 = __expf(sacc[mt][nt][2]);
                    float p11 = __expf(sacc[mt][nt][3]);
                    rsum[mt*2]     += p00 + p01;
                    rsum[mt*2 + 1] += p10 + p11;
                    Phw[r0 * 68 + (c0 >> 1)] = pack_h2(p00, p01);
                    Phw[r1 * 68 + (c0 >> 1)] = pack_h2(p10, p11);
                }
            }
        } else {
            const unsigned char* Mb = (const unsigned char*)Ms;
#pragma unroll
            for (int mt = 0; mt < 2; mt++) {
                int r0 = rbase + mt * 16 + g, r1 = r0 + 8;
#pragma unroll
                for (int nt = 0; nt < 4; nt++) {
                    int c0 = wn * 32 + nt * 8 + 2 * t;
                    float p00 = Mb[r0*128 + c0]     ? 0.f : __expf(sacc[mt][nt][0]);
                    float p01 = Mb[r0*128 + c0 + 1] ? 0.f : __expf(sacc[mt][nt][1]);
                    float p10 = Mb[r1*128 + c0]     ? 0.f : __expf(sacc[mt][nt][2]);
                    float p11 = Mb[r1*128 + c0 + 1] ? 0.f : __expf(sacc[mt][nt][3]);
                    rsum[mt*2]     += p00 + p01;
                    rsum[mt*2 + 1] += p10 + p11;
                    Phw[r0 * 68 + (c0 >> 1)] = pack_h2(p00, p01);
                    Phw[r1 * 68 + (c0 >> 1)] = pack_h2(p10, p11);
                }
            }
        }
#pragma unroll
        for (int i = 0; i < 4; i++) {
            rsum[i] += __shfl_xor_sync(0xffffffffu, rsum[i], 1);
            rsum[i] += __shfl_xor_sync(0xffffffffu, rsum[i], 2);
        }
        if (t == 0) {
            atomicAdd(&Zs[rbase + g],      rsum[0]);
            atomicAdd(&Zs[rbase + 8 + g],  rsum[1]);
            atomicAdd(&Zs[rbase + 16 + g], rsum[2]);
            atomicAdd(&Zs[rbase + 24 + g], rsum[3]);
        }
        __syncthreads();

        // ---- write E tile fp32 to gmem from Ph (coalesced) ----
        size_t abase = ((size_t)(h * BB + b) * NQ + q0) * NK + k0;
#pragma unroll
        for (int j = 0; j < 8; j++) {
            int idx = tid + j * 256;
            int r = idx >> 5, c4 = idx & 31;       // float4 column
            uint2 hw = *(uint2*)(Ph + r * PROW + c4 * 4);
            float2 f0 = __half22float2(*(__half2*)&hw.x);
            float2 f1 = __half22float2(*(__half2*)&hw.y);
            float4 v = make_float4(f0.x, f0.y, f1.x, f1.y);
            *(float4*)(attn + abase + (size_t)r * NK + c4 * 4) = v;
        }

        // ---- O += E @ V via ldmatrix(+trans) : rows rbase..+32, cols wn*16..+16 ----
        {
            int prow = ((lane >> 3) & 1) * 8 + (lane & 7);
            int pcol = (lane >> 4) * 8;
            int vrow = ((lane >> 3) & 1) * 8 + (lane & 7);  // k within 16-block
            int vcol = (lane >> 4) * 8;                     // n within 16-slice
#pragma unroll
            for (int kk = 0; kk < 8; kk++) {
                uint32_t a[2][4];
#pragma unroll
                for (int mt = 0; mt < 2; mt++)
                    ldsm_x4(a[mt],
                            pbase + ((rbase + mt * 16 + prow) * PROW + kk * 16 + pcol) * 2);
                uint32_t r4[4];
                ldsm_x4_t(r4, vbase + ((kk * 16 + vrow) * VROW + wn * 16 + vcol) * 2);
                uint32_t bf[2][2];
                bf[0][0] = r4[0]; bf[0][1] = r4[1];
                bf[1][0] = r4[2]; bf[1][1] = r4[3];
#pragma unroll
                for (int mt = 0; mt < 2; mt++)
#pragma unroll
                    for (int nt = 0; nt < 2; nt++)
                        mma16(oacc[mt][nt], a[mt], bf[nt]);
            }
        }
    }

    // ---- write 1/Z ----
    __syncthreads();
    if (tid < 64) {
        g_zi[(size_t)(b * HH + h) * NQ + q0 + tid] = 1.0f / Zs[tid];
    }

    // ---- stage O (disjoint ownership) into Ph region as float [64][68] ----
    float* Os = (float*)Ph;
#pragma unroll
    for (int mt = 0; mt < 2; mt++) {
        int r0 = rbase + mt * 16 + g, r1 = r0 + 8;
#pragma unroll
        for (int nt = 0; nt < 2; nt++) {
            int c0 = wn * 16 + nt * 8 + 2 * t;
            Os[r0 * 68 + c0]     = oacc[mt][nt][0];
            Os[r0 * 68 + c0 + 1] = oacc[mt][nt][1];
            Os[r1 * 68 + c0]     = oacc[mt][nt][2];
            Os[r1 * 68 + c0 + 1] = oacc[mt][nt][3];
        }
    }
    __syncthreads();
#pragma unroll
    for (int j = 0; j < 4; j++) {
        int idx = tid + j * 256;
        int r = idx >> 4, c = (idx & 15) * 4;
        float4 v;
        v.x = Os[r * 68 + c];
        v.y = Os[r * 68 + c + 1];
        v.z = Os[r * 68 + c + 2];
        v.w = Os[r * 68 + c + 3];
        *(float4*)(g_o + headbase + (size_t)(q0 + r) * DH + c) = v;
    }
}

// ============================================================
// Normalize attn rows: attn[row, :] *= 1/Z
// ============================================================
__global__ __launch_bounds__(256) void norm_attn_kernel(float* __restrict__ attn)
{
    int a = blockIdx.x;                 // 0 .. 16*4096-1
    int hb = a >> 12;                   // h*BB + b
    int q  = a & 4095;
    int h = hb >> 1, b = hb & 1;
    float zi = g_zi[(size_t)(b * HH + h) * NQ + q];
    float4* row = (float4*)(attn + (size_t)a * NK);
    int i = threadIdx.x;
#pragma unroll
    for (int j = 0; j < 4; j++) {
        float4 v = row[i + j * 256];
        v.x *= zi; v.y *= zi; v.z *= zi; v.w *= zi;
        row[i + j * 256] = v;
    }
}

// ============================================================
extern "C" void kernel_launch(void* const* d_in, const int* in_sizes, int n_in,
                              void* d_out, int out_size)
{
    const float* q  = (const float*)d_in[0];
    const float* k  = (const float*)d_in[1];
    const float* v  = (const float*)d_in[2];
    const unsigned char* mask = (const unsigned char*)d_in[3];
    const float* Wq = (const float*)d_in[4];
    const float* bq = (const float*)d_in[5];
    const float* Wk = (const float*)d_in[6];
    const float* bk = (const float*)d_in[7];
    const float* Wv = (const float*)d_in[8];
    const float* bv = (const float*)d_in[9];
    const float* Wo = (const float*)d_in[10];
    const float* bo = (const float*)d_in[11];

    float* out  = (float*)d_out;
    float* attn = out;                                    // [16, 4096, 4096]
    float* outp = out + (size_t)HH * BB * NQ * NK;        // [2, 4096, 512]

    proj_head_kernel<<<dim3(64, 8), 256>>>(q, Wq, bq, 0);
    proj_head_kernel<<<dim3(64, 8), 256>>>(k, Wk, bk, 1);
    proj_head_kernel<<<dim3(64, 8), 256>>>(v, Wv, bv, 2);

    cudaFuncSetAttribute(attn_kernel, cudaFuncAttributeMaxDynamicSharedMemorySize, SMEM_BYTES);
    attn_kernel<<<dim3(NQ / 64, BB * HH), 256, SMEM_BYTES>>>(mask, attn);

    norm_attn_kernel<<<dim3(HH * BB * NQ), 256>>>(attn);

    proj_out_kernel<<<dim3(64, 8), 256>>>(Wo, bo, outp);
}

// round 6
// speedup vs baseline: 2.4678x; 1.0948x over previous
#include <cuda_runtime.h>
#include <cuda_fp16.h>
#include <cstdint>

#define BB 2
#define HH 8
#define DH 64
#define DM 512
#define NQ 4096
#define NK 4096

// -------- scratch (no allocations allowed) --------
__device__ float g_qh[BB*HH*NQ*DH];
__device__ float g_kh[BB*HH*NK*DH];
__device__ float g_vh[BB*HH*NK*DH];
__device__ float g_o [BB*HH*NQ*DH];    // UNNORMALIZED O (E @ V)
__device__ float g_zi[BB*HH*NQ];       // 1 / rowsum(exp(S))
__device__ __half g_eh[(size_t)BB*HH*NQ*NK];   // unnormalized E, fp16 (536MB)
__device__ unsigned char g_mflags[BB*64*32];   // per-(b,qtile,ktile) mask-nonzero flag

__device__ __forceinline__ float to_tf32(float x) {
    float r;
    asm("cvt.rna.tf32.f32 %0, %1;" : "=f"(r) : "f"(x));
    return r;
}

// tf32: D += A(16x8) * B(8x8)
__device__ __forceinline__ void mma8(float* d, const float* a, const float* b) {
    asm("mma.sync.aligned.m16n8k8.row.col.f32.tf32.tf32.f32 "
        "{%0,%1,%2,%3}, {%4,%5,%6,%7}, {%8,%9}, {%0,%1,%2,%3};"
        : "+f"(d[0]), "+f"(d[1]), "+f"(d[2]), "+f"(d[3])
        : "r"(__float_as_uint(a[0])), "r"(__float_as_uint(a[1])),
          "r"(__float_as_uint(a[2])), "r"(__float_as_uint(a[3])),
          "r"(__float_as_uint(b[0])), "r"(__float_as_uint(b[1])));
}

// fp16: D(16x8,f32) += A(16x16) * B(16x8), packed half2 operands
__device__ __forceinline__ void mma16(float* d, const uint32_t* a, const uint32_t* b) {
    asm("mma.sync.aligned.m16n8k16.row.col.f32.f16.f16.f32 "
        "{%0,%1,%2,%3}, {%4,%5,%6,%7}, {%8,%9}, {%0,%1,%2,%3};"
        : "+f"(d[0]), "+f"(d[1]), "+f"(d[2]), "+f"(d[3])
        : "r"(a[0]), "r"(a[1]), "r"(a[2]), "r"(a[3]),
          "r"(b[0]), "r"(b[1]));
}

__device__ __forceinline__ void ldsm_x4(uint32_t* r, uint32_t addr) {
    asm volatile("ldmatrix.sync.aligned.m8n8.x4.shared.b16 {%0,%1,%2,%3}, [%4];"
        : "=r"(r[0]), "=r"(r[1]), "=r"(r[2]), "=r"(r[3]) : "r"(addr));
}
__device__ __forceinline__ void ldsm_x4_t(uint32_t* r, uint32_t addr) {
    asm volatile("ldmatrix.sync.aligned.m8n8.x4.trans.shared.b16 {%0,%1,%2,%3}, [%4];"
        : "=r"(r[0]), "=r"(r[1]), "=r"(r[2]), "=r"(r[3]) : "r"(addr));
}

__device__ __forceinline__ uint32_t pack_h2(float x, float y) {
    __half2 h = __floats2half2_rn(x, y);
    return *(uint32_t*)&h;
}
__device__ __forceinline__ uint32_t smem_u32(const void* p) {
    return (uint32_t)__cvta_generic_to_shared(p);
}

// ============================================================
// Mask tile scan: flag[b][qt][kt] = any nonzero in 64x128 tile
// ============================================================
__global__ __launch_bounds__(256) void mask_scan_kernel(const unsigned char* __restrict__ mask)
{
    int bid = blockIdx.x;               // 0..4095
    int b  = bid >> 11;
    int qt = (bid >> 5) & 63;
    int kt = bid & 31;
    const uint4* s = (const uint4*)(mask + (size_t)b * NQ * NK
                                    + (size_t)(qt * 64 + (threadIdx.x >> 2)) * NK
                                    + kt * 128 + (threadIdx.x & 3) * 32);
    uint4 a = s[0], c = s[1];
    unsigned v = a.x | a.y | a.z | a.w | c.x | c.y | c.z | c.w;
#pragma unroll
    for (int o = 16; o > 0; o >>= 1) v |= __shfl_xor_sync(0xffffffffu, v, o);
    __shared__ unsigned sflag;
    if (threadIdx.x == 0) sflag = 0u;
    __syncthreads();
    if ((threadIdx.x & 31) == 0 && v) atomicOr(&sflag, 1u);
    __syncthreads();
    if (threadIdx.x == 0) g_mflags[bid] = (unsigned char)(sflag != 0u);
}

// ============================================================
// QKV projection (tf32): Y[b,h,n,d] = X @ W^T + bias, head-major scatter.
// ============================================================
__global__ __launch_bounds__(256) void proj_head_kernel(
    const float* __restrict__ X, const float* __restrict__ W,
    const float* __restrict__ bias, int sel)
{
    float* dst = sel == 0 ? g_qh : (sel == 1 ? g_kh : g_vh);
    __shared__ float As[128][36];
    __shared__ float Ws[64][36];
    int tid = threadIdx.x;
    int lane = tid & 31, warp = tid >> 5;
    int g = lane >> 2, t = lane & 3;
    int wm = warp >> 1, wn = warp & 1;
    int m0 = blockIdx.x * 128;
    int h  = blockIdx.y;

    float acc[2][4][4];
#pragma unroll
    for (int i = 0; i < 2; i++)
#pragma unroll
        for (int j = 0; j < 4; j++)
#pragma unroll
            for (int c = 0; c < 4; c++) acc[i][j][c] = 0.f;

    int rl = tid >> 3, cl = (tid & 7) * 4;
    for (int k0 = 0; k0 < DM; k0 += 32) {
#pragma unroll
        for (int i = 0; i < 4; i++) {
            int r = rl + i * 32;
            float4 v = *(const float4*)(X + (size_t)(m0 + r) * DM + k0 + cl);
            As[r][cl]   = to_tf32(v.x);
            As[r][cl+1] = to_tf32(v.y);
            As[r][cl+2] = to_tf32(v.z);
            As[r][cl+3] = to_tf32(v.w);
        }
#pragma unroll
        for (int i = 0; i < 2; i++) {
            int r = rl + i * 32;
            float4 v = *(const float4*)(W + (size_t)(h * 64 + r) * DM + k0 + cl);
            Ws[r][cl]   = to_tf32(v.x);
            Ws[r][cl+1] = to_tf32(v.y);
            Ws[r][cl+2] = to_tf32(v.z);
            Ws[r][cl+3] = to_tf32(v.w);
        }
        __syncthreads();
#pragma unroll
        for (int kk = 0; kk < 4; kk++) {
            float a[2][4];
#pragma unroll
            for (int mt = 0; mt < 2; mt++) {
                int rb = wm * 32 + mt * 16;
                a[mt][0] = As[rb + g][kk*8 + t];
                a[mt][1] = As[rb + 8 + g][kk*8 + t];
                a[mt][2] = As[rb + g][kk*8 + t + 4];
                a[mt][3] = As[rb + 8 + g][kk*8 + t + 4];
            }
            float bf[4][2];
#pragma unroll
            for (int nt = 0; nt < 4; nt++) {
                int nl = wn * 32 + nt * 8 + g;
                bf[nt][0] = Ws[nl][kk*8 + t];
                bf[nt][1] = Ws[nl][kk*8 + t + 4];
            }
#pragma unroll
            for (int mt = 0; mt < 2; mt++)
#pragma unroll
                for (int nt = 0; nt < 4; nt++)
                    mma8(acc[mt][nt], a[mt], bf[nt]);
        }
        __syncthreads();
    }
#pragma unroll
    for (int mt = 0; mt < 2; mt++) {
        int r0 = m0 + wm * 32 + mt * 16 + g;
        int r1 = r0 + 8;
#pragma unroll
        for (int nt = 0; nt < 4; nt++) {
            int col = wn * 32 + nt * 8 + 2 * t;
            float b0v = bias[h * 64 + col], b1v = bias[h * 64 + col + 1];
            int b_ = r0 >> 12, q_ = r0 & 4095;
            float* p = dst + (size_t)((b_ * HH + h) * NQ + q_) * DH + col;
            p[0] = acc[mt][nt][0] + b0v;
            p[1] = acc[mt][nt][1] + b1v;
            b_ = r1 >> 12; q_ = r1 & 4095;
            p = dst + (size_t)((b_ * HH + h) * NQ + q_) * DH + col;
            p[0] = acc[mt][nt][2] + b0v;
            p[1] = acc[mt][nt][3] + b1v;
        }
    }
}

// ============================================================
// Output projection (tf32): output = (concat_heads(g_o) * invZ) @ Wo^T + bo
// ============================================================
__global__ __launch_bounds__(256) void proj_out_kernel(
    const float* __restrict__ W, const float* __restrict__ bias,
    float* __restrict__ Y)
{
    __shared__ float As[128][36];
    __shared__ float Ws[64][36];
    int tid = threadIdx.x;
    int lane = tid & 31, warp = tid >> 5;
    int g = lane >> 2, t = lane & 3;
    int wm = warp >> 1, wn = warp & 1;
    int m0 = blockIdx.x * 128;
    int n0 = blockIdx.y * 64;

    float acc[2][4][4];
#pragma unroll
    for (int i = 0; i < 2; i++)
#pragma unroll
        for (int j = 0; j < 4; j++)
#pragma unroll
            for (int c = 0; c < 4; c++) acc[i][j][c] = 0.f;

    int rl = tid >> 3, cl = (tid & 7) * 4;
    for (int k0 = 0; k0 < DM; k0 += 32) {
        int head = k0 >> 6;
        int dd = (k0 & 63) + cl;
#pragma unroll
        for (int i = 0; i < 4; i++) {
            int r = rl + i * 32;
            int row = m0 + r;
            int b_ = row >> 12, q_ = row & 4095;
            size_t hb = (size_t)(b_ * HH + head) * NQ + q_;
            float zi = g_zi[hb];
            float4 v = *(const float4*)(g_o + hb * DH + dd);
            As[r][cl]   = to_tf32(v.x * zi);
            As[r][cl+1] = to_tf32(v.y * zi);
            As[r][cl+2] = to_tf32(v.z * zi);
            As[r][cl+3] = to_tf32(v.w * zi);
        }
#pragma unroll
        for (int i = 0; i < 2; i++) {
            int r = rl + i * 32;
            float4 v = *(const float4*)(W + (size_t)(n0 + r) * DM + k0 + cl);
            Ws[r][cl]   = to_tf32(v.x);
            Ws[r][cl+1] = to_tf32(v.y);
            Ws[r][cl+2] = to_tf32(v.z);
            Ws[r][cl+3] = to_tf32(v.w);
        }
        __syncthreads();
#pragma unroll
        for (int kk = 0; kk < 4; kk++) {
            float a[2][4];
#pragma unroll
            for (int mt = 0; mt < 2; mt++) {
                int rb = wm * 32 + mt * 16;
                a[mt][0] = As[rb + g][kk*8 + t];
                a[mt][1] = As[rb + 8 + g][kk*8 + t];
                a[mt][2] = As[rb + g][kk*8 + t + 4];
                a[mt][3] = As[rb + 8 + g][kk*8 + t + 4];
            }
            float bf[4][2];
#pragma unroll
            for (int nt = 0; nt < 4; nt++) {
                int nl = wn * 32 + nt * 8 + g;
                bf[nt][0] = Ws[nl][kk*8 + t];
                bf[nt][1] = Ws[nl][kk*8 + t + 4];
            }
#pragma unroll
            for (int mt = 0; mt < 2; mt++)
#pragma unroll
                for (int nt = 0; nt < 4; nt++)
                    mma8(acc[mt][nt], a[mt], bf[nt]);
        }
        __syncthreads();
    }
#pragma unroll
    for (int mt = 0; mt < 2; mt++) {
        int r0 = m0 + wm * 32 + mt * 16 + g;
        int r1 = r0 + 8;
#pragma unroll
        for (int nt = 0; nt < 4; nt++) {
            int col = wn * 32 + nt * 8 + 2 * t;
            float b0v = bias[n0 + col], b1v = bias[n0 + col + 1];
            float* p = Y + (size_t)r0 * DM + n0 + col;
            p[0] = acc[mt][nt][0] + b0v;
            p[1] = acc[mt][nt][1] + b1v;
            p = Y + (size_t)r1 * DM + n0 + col;
            p[0] = acc[mt][nt][2] + b0v;
            p[1] = acc[mt][nt][3] + b1v;
        }
    }
}

// ============================================================
// Attention, fp16 mma + ldmatrix. 256 thr, 64-row Q tile, k-tile 128.
// E staged fp16 in smem; written fp16 to g_eh scratch. Mask tile loaded
// only if precomputed flag set.
// ============================================================
#define QH_OFF   0                     // half [64][72]   =  9216
#define KH_OFF   9216                  // half [128][72]  = 18432
#define VH_OFF   27648                 // half [128][72]  = 18432
#define PH_OFF   46080                 // half [64][136]  = 17408  (reused as float Os[64][68])
#define ZS_OFF   63488                 // float [64]
#define MS_OFF   63744                 // u32 [64][32]    =  8192
#define SMEM_BYTES 71936

#define QROW 72
#define KROW 72
#define VROW 72
#define PROW 136

__global__ __launch_bounds__(256, 2) void attn_kernel(const unsigned char* __restrict__ mask)
{
    extern __shared__ char smraw[];
    __half* Qh = (__half*)(smraw + QH_OFF);
    __half* Kh = (__half*)(smraw + KH_OFF);
    __half* Vh = (__half*)(smraw + VH_OFF);
    __half* Ph = (__half*)(smraw + PH_OFF);
    float*  Zs = (float*)(smraw + ZS_OFF);
    unsigned int* Ms = (unsigned int*)(smraw + MS_OFF);
    uint32_t* Phw = (uint32_t*)Ph;

    int tid = threadIdx.x;
    int lane = tid & 31, warp = tid >> 5;
    int g = lane >> 2, t = lane & 3;
    int wm = warp >> 2;   // 0..1
    int wn = warp & 3;    // 0..3
    int q0 = blockIdx.x * 64;
    int bh = blockIdx.y;
    int b = bh >> 3, h = bh & 7;
    size_t headbase = (size_t)(b * HH + h) * NQ * DH;
    const unsigned char* mbase = mask + (size_t)(b * NQ + q0) * NK;
    int mfbase = b * 2048 + blockIdx.x * 32;
    int rbase = wm * 32;

    uint32_t qbase = smem_u32(Qh);
    uint32_t kbase = smem_u32(Kh);
    uint32_t vbase = smem_u32(Vh);
    uint32_t pbase = smem_u32(Ph);

    // ---- load Q tile as half, pre-scaled by 1/8 ----
#pragma unroll
    for (int j = 0; j < 4; j++) {
        int idx = tid + j * 256;
        int r = idx >> 4, c = (idx & 15) * 4;
        float4 v = *(const float4*)(g_qh + headbase + (size_t)(q0 + r) * DH + c);
        uint2 w;
        w.x = pack_h2(v.x * 0.125f, v.y * 0.125f);
        w.y = pack_h2(v.z * 0.125f, v.w * 0.125f);
        *(uint2*)(Qh + r * QROW + c) = w;
    }
    if (tid < 64) Zs[tid] = 0.f;
    __syncthreads();

    // ---- hoist Q A-fragments ----
    uint32_t qa[2][4][4];
    {
        int qrow = ((lane >> 3) & 1) * 8 + (lane & 7);
        int qcol = (lane >> 4) * 8;
#pragma unroll
        for (int mt = 0; mt < 2; mt++)
#pragma unroll
            for (int kk = 0; kk < 4; kk++)
                ldsm_x4(qa[mt][kk],
                        qbase + ((rbase + mt * 16 + qrow) * QROW + kk * 16 + qcol) * 2);
    }

    float oacc[2][2][4];
#pragma unroll
    for (int i = 0; i < 2; i++)
#pragma unroll
        for (int j = 0; j < 2; j++)
#pragma unroll
            for (int c = 0; c < 4; c++) oacc[i][j][c] = 0.f;

    for (int kt = 0; kt < NK / 128; kt++) {
        int k0 = kt * 128;
        unsigned char mflag = g_mflags[mfbase + kt];
        __syncthreads();
        // ---- load K and V tiles as half ----
#pragma unroll
        for (int j = 0; j < 8; j++) {
            int idx = tid + j * 256;
            int r = idx >> 4, c = (idx & 15) * 4;
            float4 v = *(const float4*)(g_kh + headbase + (size_t)(k0 + r) * DH + c);
            uint2 w;
            w.x = pack_h2(v.x, v.y);
            w.y = pack_h2(v.z, v.w);
            *(uint2*)(Kh + r * KROW + c) = w;
            float4 u = *(const float4*)(g_vh + headbase + (size_t)(k0 + r) * DH + c);
            uint2 w2;
            w2.x = pack_h2(u.x, u.y);
            w2.y = pack_h2(u.z, u.w);
            *(uint2*)(Vh + r * VROW + c) = w2;
        }
        // ---- mask tile only if flagged ----
        if (mflag) {
            int r = tid >> 2, cb = (tid & 3) * 8;
            const uint4* src = (const uint4*)(mbase + (size_t)r * NK + k0 + cb * 4);
            uint4 m0 = src[0], m1 = src[1];
            *(uint4*)(Ms + r * 32 + cb)     = m0;
            *(uint4*)(Ms + r * 32 + cb + 4) = m1;
        }
        __syncthreads();

        // ---- S = Q K^T ----
        float sacc[2][4][4];
#pragma unroll
        for (int i = 0; i < 2; i++)
#pragma unroll
            for (int j = 0; j < 4; j++)
#pragma unroll
                for (int c = 0; c < 4; c++) sacc[i][j][c] = 0.f;
        {
            int kn = (lane >> 4) * 8 + (lane & 7);
            int kc = ((lane >> 3) & 1) * 8;
#pragma unroll
            for (int kk = 0; kk < 4; kk++) {
                uint32_t bf[4][2];
#pragma unroll
                for (int half_n = 0; half_n < 2; half_n++) {
                    uint32_t r4[4];
                    ldsm_x4(r4, kbase + ((wn * 32 + half_n * 16 + kn) * KROW + kk * 16 + kc) * 2);
                    bf[half_n * 2][0]     = r4[0];
                    bf[half_n * 2][1]     = r4[1];
                    bf[half_n * 2 + 1][0] = r4[2];
                    bf[half_n * 2 + 1][1] = r4[3];
                }
#pragma unroll
                for (int mt = 0; mt < 2; mt++)
#pragma unroll
                    for (int nt = 0; nt < 4; nt++)
                        mma16(sacc[mt][nt], qa[mt][kk], bf[nt]);
            }
        }

        // ---- E = exp(S); Z accumulate; stage fp16 ----
        float rsum[4] = {0.f, 0.f, 0.f, 0.f};
        if (!mflag) {
#pragma unroll
            for (int mt = 0; mt < 2; mt++) {
                int r0 = rbase + mt * 16 + g, r1 = r0 + 8;
#pragma unroll
                for (int nt = 0; nt < 4; nt++) {
                    int c0 = wn * 32 + nt * 8 + 2 * t;
                    float p00 = __expf(sacc[mt][nt][0]);
                    float p01 = __expf(sacc[mt][nt][1]);
                    float p10 = __expf(sacc[mt][nt][2]);
                    float p11 = __expf(sacc[mt][nt][3]);
                    rsum[mt*2]     += p00 + p01;
                    rsum[mt*2 + 1] += p10 + p11;
                    Phw[r0 * 68 + (c0 >> 1)] = pack_h2(p00, p01);
                    Phw[r1 * 68 + (c0 >> 1)] = pack_h2(p10, p11);
                }
            }
        } else {
            const unsigned char* Mb = (const unsigned char*)Ms;
#pragma unroll
            for (int mt = 0; mt < 2; mt++) {
                int r0 = rbase + mt * 16 + g, r1 = r0 + 8;
#pragma unroll
                for (int nt = 0; nt < 4; nt++) {
                    int c0 = wn * 32 + nt * 8 + 2 * t;
                    float p00 = Mb[r0*128 + c0]     ? 0.f : __expf(sacc[mt][nt][0]);
                    float p01 = Mb[r0*128 + c0 + 1] ? 0.f : __expf(sacc[mt][nt][1]);
                    float p10 = Mb[r1*128 + c0]     ? 0.f : __expf(sacc[mt][nt][2]);
                    float p11 = Mb[r1*128 + c0 + 1] ? 0.f : __expf(sacc[mt][nt][3]);
                    rsum[mt*2]     += p00 + p01;
                    rsum[mt*2 + 1] += p10 + p11;
                    Phw[r0 * 68 + (c0 >> 1)] = pack_h2(p00, p01);
                    Phw[r1 * 68 + (c0 >> 1)] = pack_h2(p10, p11);
                }
            }
        }
#pragma unroll
        for (int i = 0; i < 4; i++) {
            rsum[i] += __shfl_xor_sync(0xffffffffu, rsum[i], 1);
            rsum[i] += __shfl_xor_sync(0xffffffffu, rsum[i], 2);
        }
        if (t == 0) {
            atomicAdd(&Zs[rbase + g],      rsum[0]);
            atomicAdd(&Zs[rbase + 8 + g],  rsum[1]);
            atomicAdd(&Zs[rbase + 16 + g], rsum[2]);
            atomicAdd(&Zs[rbase + 24 + g], rsum[3]);
        }
        __syncthreads();

        // ---- write E tile fp16 to scratch (coalesced uint4) ----
        size_t ebase = ((size_t)(h * BB + b) * NQ + q0) * NK + k0;
#pragma unroll
        for (int j = 0; j < 4; j++) {
            int idx = tid + j * 256;
            int r = idx >> 4, c16 = idx & 15;
            uint4 v = *(uint4*)(Ph + r * PROW + c16 * 8);
            *(uint4*)((__half*)g_eh + ebase + (size_t)r * NK + c16 * 8) = v;
        }

        // ---- O += E @ V via ldmatrix ----
        {
            int prow = ((lane >> 3) & 1) * 8 + (lane & 7);
            int pcol = (lane >> 4) * 8;
            int vrow = ((lane >> 3) & 1) * 8 + (lane & 7);
            int vcol = (lane >> 4) * 8;
#pragma unroll
            for (int kk = 0; kk < 8; kk++) {
                uint32_t a[2][4];
#pragma unroll
                for (int mt = 0; mt < 2; mt++)
                    ldsm_x4(a[mt],
                            pbase + ((rbase + mt * 16 + prow) * PROW + kk * 16 + pcol) * 2);
                uint32_t r4[4];
                ldsm_x4_t(r4, vbase + ((kk * 16 + vrow) * VROW + wn * 16 + vcol) * 2);
                uint32_t bf[2][2];
                bf[0][0] = r4[0]; bf[0][1] = r4[1];
                bf[1][0] = r4[2]; bf[1][1] = r4[3];
#pragma unroll
                for (int mt = 0; mt < 2; mt++)
#pragma unroll
                    for (int nt = 0; nt < 2; nt++)
                        mma16(oacc[mt][nt], a[mt], bf[nt]);
            }
        }
    }

    // ---- write 1/Z ----
    __syncthreads();
    if (tid < 64) {
        g_zi[(size_t)(b * HH + h) * NQ + q0 + tid] = 1.0f / Zs[tid];
    }

    // ---- stage O (disjoint), coalesced write to g_o ----
    float* Os = (float*)Ph;
#pragma unroll
    for (int mt = 0; mt < 2; mt++) {
        int r0 = rbase + mt * 16 + g, r1 = r0 + 8;
#pragma unroll
        for (int nt = 0; nt < 2; nt++) {
            int c0 = wn * 16 + nt * 8 + 2 * t;
            Os[r0 * 68 + c0]     = oacc[mt][nt][0];
            Os[r0 * 68 + c0 + 1] = oacc[mt][nt][1];
            Os[r1 * 68 + c0]     = oacc[mt][nt][2];
            Os[r1 * 68 + c0 + 1] = oacc[mt][nt][3];
        }
    }
    __syncthreads();
#pragma unroll
    for (int j = 0; j < 4; j++) {
        int idx = tid + j * 256;
        int r = idx >> 4, c = (idx & 15) * 4;
        float4 v;
        v.x = Os[r * 68 + c];
        v.y = Os[r * 68 + c + 1];
        v.z = Os[r * 68 + c + 2];
        v.w = Os[r * 68 + c + 3];
        *(float4*)(g_o + headbase + (size_t)(q0 + r) * DH + c) = v;
    }
}

// ============================================================
// Finalize attn: attn[a, :] = fp32(g_eh[a, :]) * (1/Z)
// ============================================================
__global__ __launch_bounds__(256) void norm_attn_kernel(float* __restrict__ attn)
{
    int a = blockIdx.x;                 // 0 .. 65535
    int hb = a >> 12;                   // h*BB + b
    int q  = a & 4095;
    int h = hb >> 1, b = hb & 1;
    float zi = g_zi[(size_t)(b * HH + h) * NQ + q];
    const uint4* src = (const uint4*)((const __half*)g_eh + (size_t)a * NK);
    float4* dst = (float4*)(attn + (size_t)a * NK);
    int i = threadIdx.x;
#pragma unroll
    for (int j = 0; j < 2; j++) {
        int idx = i + j * 256;
        uint4 hv = src[idx];
        __half2* hp = (__half2*)&hv;
        float2 f0 = __half22float2(hp[0]);
        float2 f1 = __half22float2(hp[1]);
        float2 f2 = __half22float2(hp[2]);
        float2 f3 = __half22float2(hp[3]);
        dst[idx * 2]     = make_float4(f0.x * zi, f0.y * zi, f1.x * zi, f1.y * zi);
        dst[idx * 2 + 1] = make_float4(f2.x * zi, f2.y * zi, f3.x * zi, f3.y * zi);
    }
}

// ============================================================
extern "C" void kernel_launch(void* const* d_in, const int* in_sizes, int n_in,
                              void* d_out, int out_size)
{
    const float* q  = (const float*)d_in[0];
    const float* k  = (const float*)d_in[1];
    const float* v  = (const float*)d_in[2];
    const unsigned char* mask = (const unsigned char*)d_in[3];
    const float* Wq = (const float*)d_in[4];
    const float* bq = (const float*)d_in[5];
    const float* Wk = (const float*)d_in[6];
    const float* bk = (const float*)d_in[7];
    const float* Wv = (const float*)d_in[8];
    const float* bv = (const float*)d_in[9];
    const float* Wo = (const float*)d_in[10];
    const float* bo = (const float*)d_in[11];

    float* out  = (float*)d_out;
    float* attn = out;                                    // [16, 4096, 4096]
    float* outp = out + (size_t)HH * BB * NQ * NK;        // [2, 4096, 512]

    mask_scan_kernel<<<dim3(BB * 64 * 32), 256>>>(mask);
    proj_head_kernel<<<dim3(64, 8), 256>>>(q, Wq, bq, 0);
    proj_head_kernel<<<dim3(64, 8), 256>>>(k, Wk, bk, 1);
    proj_head_kernel<<<dim3(64, 8), 256>>>(v, Wv, bv, 2);

    cudaFuncSetAttribute(attn_kernel, cudaFuncAttributeMaxDynamicSharedMemorySize, SMEM_BYTES);
    attn_kernel<<<dim3(NQ / 64, BB * HH), 256, SMEM_BYTES>>>(mask);

    norm_attn_kernel<<<dim3(HH * BB * NQ), 256>>>(attn);

    proj_out_kernel<<<dim3(64, 8), 256>>>(Wo, bo, outp);
}

// round 7
// speedup vs baseline: 3.0613x; 1.2405x over previous
#include <cuda_runtime.h>
#include <cuda_fp16.h>
#include <cstdint>

#define BB 2
#define HH 8
#define DH 64
#define DM 512
#define NQ 4096
#define NK 4096

// -------- scratch (no allocations allowed) --------
__device__ __half g_qh[BB*HH*NQ*DH];
__device__ __half g_kh[BB*HH*NK*DH];
__device__ __half g_vh[BB*HH*NK*DH];
__device__ float  g_o [BB*HH*NQ*DH];           // UNNORMALIZED O (E @ V)
__device__ float  g_zi[BB*HH*NQ];              // 1 / rowsum(exp(S))
__device__ __half g_eh[(size_t)BB*HH*NQ*NK];   // unnormalized E, fp16
__device__ unsigned char g_mflags[BB*64*32];   // per-(b,qtile,ktile) mask flag

__device__ __forceinline__ float to_tf32(float x) {
    float r;
    asm("cvt.rna.tf32.f32 %0, %1;" : "=f"(r) : "f"(x));
    return r;
}

// tf32: D += A(16x8) * B(8x8)
__device__ __forceinline__ void mma8(float* d, const float* a, const float* b) {
    asm("mma.sync.aligned.m16n8k8.row.col.f32.tf32.tf32.f32 "
        "{%0,%1,%2,%3}, {%4,%5,%6,%7}, {%8,%9}, {%0,%1,%2,%3};"
        : "+f"(d[0]), "+f"(d[1]), "+f"(d[2]), "+f"(d[3])
        : "r"(__float_as_uint(a[0])), "r"(__float_as_uint(a[1])),
          "r"(__float_as_uint(a[2])), "r"(__float_as_uint(a[3])),
          "r"(__float_as_uint(b[0])), "r"(__float_as_uint(b[1])));
}

// fp16: D(16x8,f32) += A(16x16) * B(16x8)
__device__ __forceinline__ void mma16(float* d, const uint32_t* a, const uint32_t* b) {
    asm("mma.sync.aligned.m16n8k16.row.col.f32.f16.f16.f32 "
        "{%0,%1,%2,%3}, {%4,%5,%6,%7}, {%8,%9}, {%0,%1,%2,%3};"
        : "+f"(d[0]), "+f"(d[1]), "+f"(d[2]), "+f"(d[3])
        : "r"(a[0]), "r"(a[1]), "r"(a[2]), "r"(a[3]),
          "r"(b[0]), "r"(b[1]));
}

__device__ __forceinline__ void ldsm_x4(uint32_t* r, uint32_t addr) {
    asm volatile("ldmatrix.sync.aligned.m8n8.x4.shared.b16 {%0,%1,%2,%3}, [%4];"
        : "=r"(r[0]), "=r"(r[1]), "=r"(r[2]), "=r"(r[3]) : "r"(addr));
}
__device__ __forceinline__ void ldsm_x4_t(uint32_t* r, uint32_t addr) {
    asm volatile("ldmatrix.sync.aligned.m8n8.x4.trans.shared.b16 {%0,%1,%2,%3}, [%4];"
        : "=r"(r[0]), "=r"(r[1]), "=r"(r[2]), "=r"(r[3]) : "r"(addr));
}

__device__ __forceinline__ void cpa16(uint32_t dst, const void* src) {
    asm volatile("cp.async.cg.shared.global [%0], [%1], 16;" :: "r"(dst), "l"(src));
}
__device__ __forceinline__ void cpa_commit() {
    asm volatile("cp.async.commit_group;" ::: "memory");
}
__device__ __forceinline__ void cpa_wait0() {
    asm volatile("cp.async.wait_group 0;" ::: "memory");
}

__device__ __forceinline__ uint32_t pack_h2(float x, float y) {
    __half2 h = __floats2half2_rn(x, y);
    return *(uint32_t*)&h;
}
__device__ __forceinline__ uint32_t smem_u32(const void* p) {
    return (uint32_t)__cvta_generic_to_shared(p);
}

// ============================================================
// Mask tile scan: flag[b][qt][kt] = any nonzero in 64x128 tile
// ============================================================
__global__ __launch_bounds__(256) void mask_scan_kernel(const unsigned char* __restrict__ mask)
{
    int bid = blockIdx.x;               // 0..4095
    int b  = bid >> 11;
    int qt = (bid >> 5) & 63;
    int kt = bid & 31;
    const uint4* s = (const uint4*)(mask + (size_t)b * NQ * NK
                                    + (size_t)(qt * 64 + (threadIdx.x >> 2)) * NK
                                    + kt * 128 + (threadIdx.x & 3) * 32);
    uint4 a = s[0], c = s[1];
    unsigned v = a.x | a.y | a.z | a.w | c.x | c.y | c.z | c.w;
#pragma unroll
    for (int o = 16; o > 0; o >>= 1) v |= __shfl_xor_sync(0xffffffffu, v, o);
    __shared__ unsigned sflag;
    if (threadIdx.x == 0) sflag = 0u;
    __syncthreads();
    if ((threadIdx.x & 31) == 0 && v) atomicOr(&sflag, 1u);
    __syncthreads();
    if (threadIdx.x == 0) g_mflags[bid] = (unsigned char)(sflag != 0u);
}

// ============================================================
// QKV projection (tf32): Y = X @ W^T + bias -> fp16, head-major scatter.
// ============================================================
__global__ __launch_bounds__(256) void proj_head_kernel(
    const float* __restrict__ X, const float* __restrict__ W,
    const float* __restrict__ bias, int sel)
{
    __half* dst = sel == 0 ? g_qh : (sel == 1 ? g_kh : g_vh);
    __shared__ float As[128][36];
    __shared__ float Ws[64][36];
    int tid = threadIdx.x;
    int lane = tid & 31, warp = tid >> 5;
    int g = lane >> 2, t = lane & 3;
    int wm = warp >> 1, wn = warp & 1;
    int m0 = blockIdx.x * 128;
    int h  = blockIdx.y;

    float acc[2][4][4];
#pragma unroll
    for (int i = 0; i < 2; i++)
#pragma unroll
        for (int j = 0; j < 4; j++)
#pragma unroll
            for (int c = 0; c < 4; c++) acc[i][j][c] = 0.f;

    int rl = tid >> 3, cl = (tid & 7) * 4;
    for (int k0 = 0; k0 < DM; k0 += 32) {
#pragma unroll
        for (int i = 0; i < 4; i++) {
            int r = rl + i * 32;
            float4 v = *(const float4*)(X + (size_t)(m0 + r) * DM + k0 + cl);
            As[r][cl]   = to_tf32(v.x);
            As[r][cl+1] = to_tf32(v.y);
            As[r][cl+2] = to_tf32(v.z);
            As[r][cl+3] = to_tf32(v.w);
        }
#pragma unroll
        for (int i = 0; i < 2; i++) {
            int r = rl + i * 32;
            float4 v = *(const float4*)(W + (size_t)(h * 64 + r) * DM + k0 + cl);
            Ws[r][cl]   = to_tf32(v.x);
            Ws[r][cl+1] = to_tf32(v.y);
            Ws[r][cl+2] = to_tf32(v.z);
            Ws[r][cl+3] = to_tf32(v.w);
        }
        __syncthreads();
#pragma unroll
        for (int kk = 0; kk < 4; kk++) {
            float a[2][4];
#pragma unroll
            for (int mt = 0; mt < 2; mt++) {
                int rb = wm * 32 + mt * 16;
                a[mt][0] = As[rb + g][kk*8 + t];
                a[mt][1] = As[rb + 8 + g][kk*8 + t];
                a[mt][2] = As[rb + g][kk*8 + t + 4];
                a[mt][3] = As[rb + 8 + g][kk*8 + t + 4];
            }
            float bf[4][2];
#pragma unroll
            for (int nt = 0; nt < 4; nt++) {
                int nl = wn * 32 + nt * 8 + g;
                bf[nt][0] = Ws[nl][kk*8 + t];
                bf[nt][1] = Ws[nl][kk*8 + t + 4];
            }
#pragma unroll
            for (int mt = 0; mt < 2; mt++)
#pragma unroll
                for (int nt = 0; nt < 4; nt++)
                    mma8(acc[mt][nt], a[mt], bf[nt]);
        }
        __syncthreads();
    }
#pragma unroll
    for (int mt = 0; mt < 2; mt++) {
        int r0 = m0 + wm * 32 + mt * 16 + g;
        int r1 = r0 + 8;
#pragma unroll
        for (int nt = 0; nt < 4; nt++) {
            int col = wn * 32 + nt * 8 + 2 * t;
            float b0v = bias[h * 64 + col], b1v = bias[h * 64 + col + 1];
            int b_ = r0 >> 12, q_ = r0 & 4095;
            *(uint32_t*)(dst + (size_t)((b_ * HH + h) * NQ + q_) * DH + col) =
                pack_h2(acc[mt][nt][0] + b0v, acc[mt][nt][1] + b1v);
            b_ = r1 >> 12; q_ = r1 & 4095;
            *(uint32_t*)(dst + (size_t)((b_ * HH + h) * NQ + q_) * DH + col) =
                pack_h2(acc[mt][nt][2] + b0v, acc[mt][nt][3] + b1v);
        }
    }
}

// ============================================================
// Output projection (tf32): output = (concat_heads(g_o) * invZ) @ Wo^T + bo
// ============================================================
__global__ __launch_bounds__(256) void proj_out_kernel(
    const float* __restrict__ W, const float* __restrict__ bias,
    float* __restrict__ Y)
{
    __shared__ float As[128][36];
    __shared__ float Ws[64][36];
    int tid = threadIdx.x;
    int lane = tid & 31, warp = tid >> 5;
    int g = lane >> 2, t = lane & 3;
    int wm = warp >> 1, wn = warp & 1;
    int m0 = blockIdx.x * 128;
    int n0 = blockIdx.y * 64;

    float acc[2][4][4];
#pragma unroll
    for (int i = 0; i < 2; i++)
#pragma unroll
        for (int j = 0; j < 4; j++)
#pragma unroll
            for (int c = 0; c < 4; c++) acc[i][j][c] = 0.f;

    int rl = tid >> 3, cl = (tid & 7) * 4;
    for (int k0 = 0; k0 < DM; k0 += 32) {
        int head = k0 >> 6;
        int dd = (k0 & 63) + cl;
#pragma unroll
        for (int i = 0; i < 4; i++) {
            int r = rl + i * 32;
            int row = m0 + r;
            int b_ = row >> 12, q_ = row & 4095;
            size_t hb = (size_t)(b_ * HH + head) * NQ + q_;
            float zi = g_zi[hb];
            float4 v = *(const float4*)(g_o + hb * DH + dd);
            As[r][cl]   = to_tf32(v.x * zi);
            As[r][cl+1] = to_tf32(v.y * zi);
            As[r][cl+2] = to_tf32(v.z * zi);
            As[r][cl+3] = to_tf32(v.w * zi);
        }
#pragma unroll
        for (int i = 0; i < 2; i++) {
            int r = rl + i * 32;
            float4 v = *(const float4*)(W + (size_t)(n0 + r) * DM + k0 + cl);
            Ws[r][cl]   = to_tf32(v.x);
            Ws[r][cl+1] = to_tf32(v.y);
            Ws[r][cl+2] = to_tf32(v.z);
            Ws[r][cl+3] = to_tf32(v.w);
        }
        __syncthreads();
#pragma unroll
        for (int kk = 0; kk < 4; kk++) {
            float a[2][4];
#pragma unroll
            for (int mt = 0; mt < 2; mt++) {
                int rb = wm * 32 + mt * 16;
                a[mt][0] = As[rb + g][kk*8 + t];
                a[mt][1] = As[rb + 8 + g][kk*8 + t];
                a[mt][2] = As[rb + g][kk*8 + t + 4];
                a[mt][3] = As[rb + 8 + g][kk*8 + t + 4];
            }
            float bf[4][2];
#pragma unroll
            for (int nt = 0; nt < 4; nt++) {
                int nl = wn * 32 + nt * 8 + g;
                bf[nt][0] = Ws[nl][kk*8 + t];
                bf[nt][1] = Ws[nl][kk*8 + t + 4];
            }
#pragma unroll
            for (int mt = 0; mt < 2; mt++)
#pragma unroll
                for (int nt = 0; nt < 4; nt++)
                    mma8(acc[mt][nt], a[mt], bf[nt]);
        }
        __syncthreads();
    }
#pragma unroll
    for (int mt = 0; mt < 2; mt++) {
        int r0 = m0 + wm * 32 + mt * 16 + g;
        int r1 = r0 + 8;
#pragma unroll
        for (int nt = 0; nt < 4; nt++) {
            int col = wn * 32 + nt * 8 + 2 * t;
            float b0v = bias[n0 + col], b1v = bias[n0 + col + 1];
            float* p = Y + (size_t)r0 * DM + n0 + col;
            p[0] = acc[mt][nt][0] + b0v;
            p[1] = acc[mt][nt][1] + b1v;
            p = Y + (size_t)r1 * DM + n0 + col;
            p[0] = acc[mt][nt][2] + b0v;
            p[1] = acc[mt][nt][3] + b1v;
        }
    }
}

// ============================================================
// Attention: fp16 mma + ldmatrix + cp.async double-buffered K/V.
// 256 thr, 64-row Q tile, k-tile 128. Scale 1/8 folded into exp.
// ============================================================
#define QH_OFF   0                     // half [64][72]       =  9216
#define KH_OFF   9216                  // 2 x half [128][72]  = 36864
#define VH_OFF   46080                 // 2 x half [128][72]  = 36864
#define PH_OFF   82944                 // half [64][136]      = 17408 (also float Os[64][68])
#define ZS_OFF   100352                // float [64]
#define MS_OFF   100608                // u32 [64][32]        =  8192
#define SMEM_BYTES 108800

#define QROW 72
#define KROW 72
#define VROW 72
#define PROW 136
#define KBUF 18432   // bytes per K buffer
#define VBUF 18432

__global__ __launch_bounds__(256, 2) void attn_kernel(const unsigned char* __restrict__ mask)
{
    extern __shared__ char smraw[];
    __half* Qh = (__half*)(smraw + QH_OFF);
    __half* Ph = (__half*)(smraw + PH_OFF);
    float*  Zs = (float*)(smraw + ZS_OFF);
    unsigned int* Ms = (unsigned int*)(smraw + MS_OFF);
    uint32_t* Phw = (uint32_t*)Ph;

    int tid = threadIdx.x;
    int lane = tid & 31, warp = tid >> 5;
    int g = lane >> 2, t = lane & 3;
    int wm = warp >> 2;   // 0..1
    int wn = warp & 3;    // 0..3
    int q0 = blockIdx.x * 64;
    int bh = blockIdx.y;
    int b = bh >> 3, h = bh & 7;
    size_t headbase = (size_t)(b * HH + h) * NQ * DH;
    const unsigned char* mbase = mask + (size_t)(b * NQ + q0) * NK;
    int mfbase = b * 2048 + blockIdx.x * 32;
    int rbase = wm * 32;

    uint32_t qbase = smem_u32(Qh);
    uint32_t kbase = smem_u32(smraw + KH_OFF);
    uint32_t vbase = smem_u32(smraw + VH_OFF);
    uint32_t pbase = smem_u32(Ph);

    // ---- prologue: cp.async Q tile + K/V tile 0 ----
    {
        // Q: 64 rows x 128B = 512 chunks
#pragma unroll
        for (int j = 0; j < 2; j++) {
            int idx = tid + j * 256;
            int r = idx >> 3, o = (idx & 7) * 8;
            cpa16(qbase + (r * QROW + o) * 2, g_qh + headbase + (size_t)(q0 + r) * DH + o);
        }
        // K/V tile 0: 128 rows x 128B = 1024 chunks each
#pragma unroll
        for (int j = 0; j < 4; j++) {
            int idx = tid + j * 256;
            int r = idx >> 3, o = (idx & 7) * 8;
            cpa16(kbase + (r * KROW + o) * 2, g_kh + headbase + (size_t)r * DH + o);
            cpa16(vbase + (r * VROW + o) * 2, g_vh + headbase + (size_t)r * DH + o);
        }
        cpa_commit();
    }
    if (tid < 64) Zs[tid] = 0.f;
    cpa_wait0();
    __syncthreads();

    // ---- hoist Q A-fragments ----
    uint32_t qa[2][4][4];
    {
        int qrow = ((lane >> 3) & 1) * 8 + (lane & 7);
        int qcol = (lane >> 4) * 8;
#pragma unroll
        for (int mt = 0; mt < 2; mt++)
#pragma unroll
            for (int kk = 0; kk < 4; kk++)
                ldsm_x4(qa[mt][kk],
                        qbase + ((rbase + mt * 16 + qrow) * QROW + kk * 16 + qcol) * 2);
    }

    float oacc[2][2][4];
#pragma unroll
    for (int i = 0; i < 2; i++)
#pragma unroll
        for (int j = 0; j < 2; j++)
#pragma unroll
            for (int c = 0; c < 4; c++) oacc[i][j][c] = 0.f;

    for (int kt = 0; kt < NK / 128; kt++) {
        int buf = kt & 1;
        uint32_t kb = kbase + buf * KBUF;
        uint32_t vb = vbase + buf * VBUF;
        unsigned char mflag = g_mflags[mfbase + kt];

        // ---- prefetch next K/V tile into other buffer ----
        if (kt + 1 < NK / 128) {
            int nbuf = buf ^ 1;
            const __half* ksrc = g_kh + headbase + (size_t)(kt + 1) * 128 * DH;
            const __half* vsrc = g_vh + headbase + (size_t)(kt + 1) * 128 * DH;
#pragma unroll
            for (int j = 0; j < 4; j++) {
                int idx = tid + j * 256;
                int r = idx >> 3, o = (idx & 7) * 8;
                cpa16(kbase + nbuf * KBUF + (r * KROW + o) * 2, ksrc + (size_t)r * DH + o);
                cpa16(vbase + nbuf * VBUF + (r * VROW + o) * 2, vsrc + (size_t)r * DH + o);
            }
            cpa_commit();
        }

        // ---- mask tile only if flagged ----
        if (mflag) {
            int r = tid >> 2, cb = (tid & 3) * 8;
            const uint4* src = (const uint4*)(mbase + (size_t)r * NK + kt * 128 + cb * 4);
            uint4 m0 = src[0], m1 = src[1];
            *(uint4*)(Ms + r * 32 + cb)     = m0;
            *(uint4*)(Ms + r * 32 + cb + 4) = m1;
            __syncthreads();
        }

        // ---- S = Q K^T ----
        float sacc[2][4][4];
#pragma unroll
        for (int i = 0; i < 2; i++)
#pragma unroll
            for (int j = 0; j < 4; j++)
#pragma unroll
                for (int c = 0; c < 4; c++) sacc[i][j][c] = 0.f;
        {
            int kn = (lane >> 4) * 8 + (lane & 7);
            int kc = ((lane >> 3) & 1) * 8;
#pragma unroll
            for (int kk = 0; kk < 4; kk++) {
                uint32_t bf[4][2];
#pragma unroll
                for (int half_n = 0; half_n < 2; half_n++) {
                    uint32_t r4[4];
                    ldsm_x4(r4, kb + ((wn * 32 + half_n * 16 + kn) * KROW + kk * 16 + kc) * 2);
                    bf[half_n * 2][0]     = r4[0];
                    bf[half_n * 2][1]     = r4[1];
                    bf[half_n * 2 + 1][0] = r4[2];
                    bf[half_n * 2 + 1][1] = r4[3];
                }
#pragma unroll
                for (int mt = 0; mt < 2; mt++)
#pragma unroll
                    for (int nt = 0; nt < 4; nt++)
                        mma16(sacc[mt][nt], qa[mt][kk], bf[nt]);
            }
        }

        // ---- E = exp(S/8); Z accumulate; stage fp16 ----
        const float SC = 0.125f;
        float rsum[4] = {0.f, 0.f, 0.f, 0.f};
        if (!mflag) {
#pragma unroll
            for (int mt = 0; mt < 2; mt++) {
                int r0 = rbase + mt * 16 + g, r1 = r0 + 8;
#pragma unroll
                for (int nt = 0; nt < 4; nt++) {
                    int c0 = wn * 32 + nt * 8 + 2 * t;
                    float p00 = __expf(sacc[mt][nt][0] * SC);
                    float p01 = __expf(sacc[mt][nt][1] * SC);
                    float p10 = __expf(sacc[mt][nt][2] * SC);
                    float p11 = __expf(sacc[mt][nt][3] * SC);
                    rsum[mt*2]     += p00 + p01;
                    rsum[mt*2 + 1] += p10 + p11;
                    Phw[r0 * 68 + (c0 >> 1)] = pack_h2(p00, p01);
                    Phw[r1 * 68 + (c0 >> 1)] = pack_h2(p10, p11);
                }
            }
        } else {
            const unsigned char* Mb = (const unsigned char*)Ms;
#pragma unroll
            for (int mt = 0; mt < 2; mt++) {
                int r0 = rbase + mt * 16 + g, r1 = r0 + 8;
#pragma unroll
                for (int nt = 0; nt < 4; nt++) {
                    int c0 = wn * 32 + nt * 8 + 2 * t;
                    float p00 = Mb[r0*128 + c0]     ? 0.f : __expf(sacc[mt][nt][0] * SC);
                    float p01 = Mb[r0*128 + c0 + 1] ? 0.f : __expf(sacc[mt][nt][1] * SC);
                    float p10 = Mb[r1*128 + c0]     ? 0.f : __expf(sacc[mt][nt][2] * SC);
                    float p11 = Mb[r1*128 + c0 + 1] ? 0.f : __expf(sacc[mt][nt][3] * SC);
                    rsum[mt*2]     += p00 + p01;
                    rsum[mt*2 + 1] += p10 + p11;
                    Phw[r0 * 68 + (c0 >> 1)] = pack_h2(p00, p01);
                    Phw[r1 * 68 + (c0 >> 1)] = pack_h2(p10, p11);
                }
            }
        }
#pragma unroll
        for (int i = 0; i < 4; i++) {
            rsum[i] += __shfl_xor_sync(0xffffffffu, rsum[i], 1);
            rsum[i] += __shfl_xor_sync(0xffffffffu, rsum[i], 2);
        }
        if (t == 0) {
            atomicAdd(&Zs[rbase + g],      rsum[0]);
            atomicAdd(&Zs[rbase + 8 + g],  rsum[1]);
            atomicAdd(&Zs[rbase + 16 + g], rsum[2]);
            atomicAdd(&Zs[rbase + 24 + g], rsum[3]);
        }
        __syncthreads();

        // ---- write E tile fp16 to scratch (coalesced uint4) ----
        size_t ebase = ((size_t)(h * BB + b) * NQ + q0) * NK + kt * 128;
#pragma unroll
        for (int j = 0; j < 4; j++) {
            int idx = tid + j * 256;
            int r = idx >> 4, c16 = idx & 15;
            uint4 v = *(uint4*)(Ph + r * PROW + c16 * 8);
            *(uint4*)((__half*)g_eh + ebase + (size_t)r * NK + c16 * 8) = v;
        }

        // ---- O += E @ V via ldmatrix ----
        {
            int prow = ((lane >> 3) & 1) * 8 + (lane & 7);
            int pcol = (lane >> 4) * 8;
            int vrow = ((lane >> 3) & 1) * 8 + (lane & 7);
            int vcol = (lane >> 4) * 8;
#pragma unroll
            for (int kk = 0; kk < 8; kk++) {
                uint32_t a[2][4];
#pragma unroll
                for (int mt = 0; mt < 2; mt++)
                    ldsm_x4(a[mt],
                            pbase + ((rbase + mt * 16 + prow) * PROW + kk * 16 + pcol) * 2);
                uint32_t r4[4];
                ldsm_x4_t(r4, vb + ((kk * 16 + vrow) * VROW + wn * 16 + vcol) * 2);
                uint32_t bf[2][2];
                bf[0][0] = r4[0]; bf[0][1] = r4[1];
                bf[1][0] = r4[2]; bf[1][1] = r4[3];
#pragma unroll
                for (int mt = 0; mt < 2; mt++)
#pragma unroll
                    for (int nt = 0; nt < 2; nt++)
                        mma16(oacc[mt][nt], a[mt], bf[nt]);
            }
        }

        // ---- wait for next tile's cp.async, then barrier before reuse ----
        if (kt + 1 < NK / 128) cpa_wait0();
        __syncthreads();
    }

    // ---- write 1/Z ----
    if (tid < 64) {
        g_zi[(size_t)(b * HH + h) * NQ + q0 + tid] = 1.0f / Zs[tid];
    }

    // ---- stage O (disjoint), coalesced write to g_o ----
    float* Os = (float*)Ph;
#pragma unroll
    for (int mt = 0; mt < 2; mt++) {
        int r0 = rbase + mt * 16 + g, r1 = r0 + 8;
#pragma unroll
        for (int nt = 0; nt < 2; nt++) {
            int c0 = wn * 16 + nt * 8 + 2 * t;
            Os[r0 * 68 + c0]     = oacc[mt][nt][0];
            Os[r0 * 68 + c0 + 1] = oacc[mt][nt][1];
            Os[r1 * 68 + c0]     = oacc[mt][nt][2];
            Os[r1 * 68 + c0 + 1] = oacc[mt][nt][3];
        }
    }
    __syncthreads();
#pragma unroll
    for (int j = 0; j < 4; j++) {
        int idx = tid + j * 256;
        int r = idx >> 4, c = (idx & 15) * 4;
        float4 v;
        v.x = Os[r * 68 + c];
        v.y = Os[r * 68 + c + 1];
        v.z = Os[r * 68 + c + 2];
        v.w = Os[r * 68 + c + 3];
        *(float4*)(g_o + headbase + (size_t)(q0 + r) * DH + c) = v;
    }
}

// ============================================================
// Finalize attn: attn[a, :] = fp32(g_eh[a, :]) * (1/Z)
// ============================================================
__global__ __launch_bounds__(256) void norm_attn_kernel(float* __restrict__ attn)
{
    int a = blockIdx.x;                 // 0 .. 65535
    int hb = a >> 12;                   // h*BB + b
    int q  = a & 4095;
    int h = hb >> 1, b = hb & 1;
    float zi = g_zi[(size_t)(b * HH + h) * NQ + q];
    const uint4* src = (const uint4*)((const __half*)g_eh + (size_t)a * NK);
    float4* dst = (float4*)(attn + (size_t)a * NK);
    int i = threadIdx.x;
#pragma unroll
    for (int j = 0; j < 2; j++) {
        int idx = i + j * 256;
        uint4 hv = src[idx];
        __half2* hp = (__half2*)&hv;
        float2 f0 = __half22float2(hp[0]);
        float2 f1 = __half22float2(hp[1]);
        float2 f2 = __half22float2(hp[2]);
        float2 f3 = __half22float2(hp[3]);
        dst[idx * 2]     = make_float4(f0.x * zi, f0.y * zi, f1.x * zi, f1.y * zi);
        dst[idx * 2 + 1] = make_float4(f2.x * zi, f2.y * zi, f3.x * zi, f3.y * zi);
    }
}

// ============================================================
extern "C" void kernel_launch(void* const* d_in, const int* in_sizes, int n_in,
                              void* d_out, int out_size)
{
    const float* q  = (const float*)d_in[0];
    const float* k  = (const float*)d_in[1];
    const float* v  = (const float*)d_in[2];
    const unsigned char* mask = (const unsigned char*)d_in[3];
    const float* Wq = (const float*)d_in[4];
    const float* bq = (const float*)d_in[5];
    const float* Wk = (const float*)d_in[6];
    const float* bk = (const float*)d_in[7];
    const float* Wv = (const float*)d_in[8];
    const float* bv = (const float*)d_in[9];
    const float* Wo = (const float*)d_in[10];
    const float* bo = (const float*)d_in[11];

    float* out  = (float*)d_out;
    float* attn = out;                                    // [16, 4096, 4096]
    float* outp = out + (size_t)HH * BB * NQ * NK;        // [2, 4096, 512]

    mask_scan_kernel<<<dim3(BB * 64 * 32), 256>>>(mask);
    proj_head_kernel<<<dim3(64, 8), 256>>>(q, Wq, bq, 0);
    proj_head_kernel<<<dim3(64, 8), 256>>>(k, Wk, bk, 1);
    proj_head_kernel<<<dim3(64, 8), 256>>>(v, Wv, bv, 2);

    cudaFuncSetAttribute(attn_kernel, cudaFuncAttributeMaxDynamicSharedMemorySize, SMEM_BYTES);
    attn_kernel<<<dim3(NQ / 64, BB * HH), 256, SMEM_BYTES>>>(mask);

    norm_attn_kernel<<<dim3(HH * BB * NQ), 256>>>(attn);

    proj_out_kernel<<<dim3(64, 8), 256>>>(Wo, bo, outp);
}